// round 10
// baseline (speedup 1.0000x reference)
#include <cuda_runtime.h>
#include <math.h>
#include <float.h>

// Problem constants
#define BATCH 2
#define SEQ   2048
#define CDIM  768
#define NHEAD 12
#define HDIM  64
#define MROWS (BATCH*SEQ)     // 4096
#define N3    (3*CDIM)        // 2304
#define BHN   (BATCH*NHEAD)   // 24

// Scratch (device globals; no allocation allowed)
__device__ float g_Q[BATCH*NHEAD*SEQ*HDIM];
__device__ float g_K[BATCH*NHEAD*SEQ*HDIM];
__device__ float g_V[BATCH*NHEAD*SEQ*HDIM];
__device__ float g_attn[BATCH*SEQ*CDIM];
// tf32 pre-converted operands
__device__ float g_xc[MROWS*CDIM];
__device__ float g_Wac[CDIM*N3];
__device__ float g_Wpc[CDIM*CDIM];

// ---------------------------------------------------------------------------
// helpers
// ---------------------------------------------------------------------------
__device__ __forceinline__ float tf32r(float x) {
    unsigned u;
    asm("cvt.rna.tf32.f32 %0, %1;" : "=r"(u) : "f"(x));
    return __uint_as_float(u);
}

__device__ __forceinline__ void mma_tf32(float* c, const unsigned* a, const unsigned* b) {
    asm volatile(
        "mma.sync.aligned.m16n8k8.row.col.f32.tf32.tf32.f32 "
        "{%0,%1,%2,%3},{%4,%5,%6,%7},{%8,%9},{%0,%1,%2,%3};\n"
        : "+f"(c[0]), "+f"(c[1]), "+f"(c[2]), "+f"(c[3])
        : "r"(a[0]), "r"(a[1]), "r"(a[2]), "r"(a[3]), "r"(b[0]), "r"(b[1]));
}

__device__ __forceinline__ void cp_async16(float* smem_dst, const float* gmem_src) {
    unsigned saddr = (unsigned)__cvta_generic_to_shared(smem_dst);
    asm volatile("cp.async.cg.shared.global [%0], [%1], 16;\n"
                 :: "r"(saddr), "l"(gmem_src));
}
#define CP_COMMIT() asm volatile("cp.async.commit_group;\n" ::: "memory")
#define CP_WAIT0()  asm volatile("cp.async.wait_group 0;\n" ::: "memory")
#define CP_WAIT1()  asm volatile("cp.async.wait_group 1;\n" ::: "memory")

// ---------------------------------------------------------------------------
// Kernel 0: pre-convert x, W_attn, W_proj to tf32 (unchanged)
// ---------------------------------------------------------------------------
#define XC4  (MROWS*CDIM/4)
#define WAC4 (CDIM*N3/4)
#define WPC4 (CDIM*CDIM/4)

__global__ __launch_bounds__(256) void prep_tf32_kernel(
    const float* __restrict__ x,
    const float* __restrict__ Wa,
    const float* __restrict__ Wp)
{
    const int total = XC4 + WAC4 + WPC4;
    for (int i = blockIdx.x*blockDim.x + threadIdx.x; i < total;
         i += gridDim.x*blockDim.x) {
        const float4* src;
        float4* dst;
        int j = i;
        if (j < XC4)            { src = (const float4*)x  + j; dst = (float4*)g_xc  + j; }
        else if ((j -= XC4) < WAC4) { src = (const float4*)Wa + j; dst = (float4*)g_Wac + j; }
        else { j -= WAC4;         src = (const float4*)Wp + j; dst = (float4*)g_Wpc + j; }
        float4 v = *src;
        v.x = tf32r(v.x); v.y = tf32r(v.y); v.z = tf32r(v.z); v.w = tf32r(v.w);
        *dst = v;
    }
}

// ---------------------------------------------------------------------------
// Kernel 1: QKV GEMM (unchanged from round 9)
// ---------------------------------------------------------------------------
#define AS_SZ (128*36)
#define BS_SZ (32*136)

__global__ __launch_bounds__(256, 2) void qkv_gemm_kernel(const float* __restrict__ bias)
{
    extern __shared__ __align__(16) float ds[];
    float* Asb[2] = { ds, ds + AS_SZ };
    float* Bsb[2] = { ds + 2*AS_SZ, ds + 2*AS_SZ + BS_SZ };

    const int tid = threadIdx.x;
    const int bn = blockIdx.x;
    const int bm = blockIdx.y;
    const int warp = tid >> 5;
    const int lane = tid & 31;
    const int wm = warp >> 2;
    const int wn = warp & 3;
    const int lr = lane >> 2;
    const int lc = lane & 3;

    float acc[4][4][4];
    #pragma unroll
    for (int mi = 0; mi < 4; mi++)
        #pragma unroll
        for (int ni = 0; ni < 4; ni++)
            #pragma unroll
            for (int q = 0; q < 4; q++) acc[mi][ni][q] = 0.0f;

    const int arow = tid >> 3;
    const int ac4  = (tid & 7) << 2;
    const int brow = tid >> 5;
    const int bc4  = (tid & 31) << 2;

    const float* Ag = g_xc + (size_t)(bm*128)*CDIM;
    const float* Bg = g_Wac + bn*128;

    #pragma unroll
    for (int i = 0; i < 4; i++) {
        const int r = arow + i*32;
        cp_async16(&Asb[0][r*36 + ac4], Ag + (size_t)r*CDIM + ac4);
    }
    #pragma unroll
    for (int i = 0; i < 4; i++) {
        const int r = brow + i*8;
        cp_async16(&Bsb[0][r*136 + bc4], Bg + (size_t)r*N3 + bc4);
    }
    CP_COMMIT();

    for (int it = 0; it < CDIM/32; it++) {
        const int cur = it & 1;
        CP_WAIT0();
        __syncthreads();

        if (it + 1 < CDIM/32) {
            const int k0 = (it+1)*32;
            #pragma unroll
            for (int i = 0; i < 4; i++) {
                const int r = arow + i*32;
                cp_async16(&Asb[cur^1][r*36 + ac4], Ag + (size_t)r*CDIM + k0 + ac4);
            }
            #pragma unroll
            for (int i = 0; i < 4; i++) {
                const int r = brow + i*8;
                cp_async16(&Bsb[cur^1][r*136 + bc4], Bg + (size_t)(k0 + r)*N3 + bc4);
            }
            CP_COMMIT();
        }

        const float* As = Asb[cur];
        const float* Bs = Bsb[cur];
        #pragma unroll
        for (int ks = 0; ks < 4; ks++) {
            unsigned a[4][4], b[4][2];
            const int kk = ks*8 + lc;
            #pragma unroll
            for (int mi = 0; mi < 4; mi++) {
                const int row = wm*64 + mi*16 + lr;
                a[mi][0] = __float_as_uint(As[ row   *36 + kk  ]);
                a[mi][1] = __float_as_uint(As[(row+8)*36 + kk  ]);
                a[mi][2] = __float_as_uint(As[ row   *36 + kk+4]);
                a[mi][3] = __float_as_uint(As[(row+8)*36 + kk+4]);
            }
            #pragma unroll
            for (int ni = 0; ni < 4; ni++) {
                const int coln = wn*32 + ni*8 + lr;
                b[ni][0] = __float_as_uint(Bs[(ks*8 + lc    )*136 + coln]);
                b[ni][1] = __float_as_uint(Bs[(ks*8 + lc + 4)*136 + coln]);
            }
            #pragma unroll
            for (int mi = 0; mi < 4; mi++)
                #pragma unroll
                for (int ni = 0; ni < 4; ni++)
                    mma_tf32(acc[mi][ni], a[mi], b[ni]);
        }
        __syncthreads();
    }

    #pragma unroll
    for (int mi = 0; mi < 4; mi++) {
        const int r0 = bm*128 + wm*64 + mi*16 + lr;
        const int r1 = r0 + 8;
        #pragma unroll
        for (int ni = 0; ni < 4; ni++) {
            const int n = bn*128 + wn*32 + ni*8 + 2*lc;
            const float b0 = bias[n], b1 = bias[n+1];
            const int part = n / CDIM;
            const int rr = n % CDIM;
            const int h = rr >> 6;
            const int d = rr & 63;
            float* dst = (part == 0) ? g_Q : (part == 1) ? g_K : g_V;
            {
                const int bb = r0 >> 11, t = r0 & 2047;
                float2 v;
                v.x = tf32r(acc[mi][ni][0] + b0);
                v.y = tf32r(acc[mi][ni][1] + b1);
                *(float2*)&dst[(((size_t)bb*NHEAD + h)*SEQ + t)*HDIM + d] = v;
            }
            {
                const int bb = r1 >> 11, t = r1 & 2047;
                float2 v;
                v.x = tf32r(acc[mi][ni][2] + b0);
                v.y = tf32r(acc[mi][ni][3] + b1);
                *(float2*)&dst[(((size_t)bb*NHEAD + h)*SEQ + t)*HDIM + d] = v;
            }
        }
    }
}

// ---------------------------------------------------------------------------
// Kernel 2: flash attention, tf32 mma, Bq=Bk=64, 4 warps, 4 CTAs/SM
//  3 smem buffers: K double-buffered (distance-1), V single (issued at top),
//  exp2-domain softmax, register-resident P
// Groups per tile (in order): V_kt, K_{kt+1}.  Top: wait 0 (K_kt).
// Pre-PV: wait 1 (V_kt done, K_next may fly).
// ---------------------------------------------------------------------------
#define FS 68
#define KST (64*FS)
#define SCL2 0.18033688011112042f   // 0.125 * log2(e)

__global__ __launch_bounds__(128, 4) void flash_kernel(const int* __restrict__ amask)
{
    extern __shared__ __align__(16) float dsm[];
    float* Kb[2] = { dsm, dsm + KST };
    float* Vb  = dsm + 2*KST;
    float* msk = dsm + 3*KST;   // [2][64]

    const int qt = 31 - blockIdx.x;  // heavy-first
    const int bh = blockIdx.y;
    const int b  = bh / NHEAD;
    const int h  = bh % NHEAD;

    const float* Qg = g_Q + (size_t)bh*SEQ*HDIM + qt*64*HDIM;
    const float* Kg = g_K + (size_t)bh*SEQ*HDIM;
    const float* Vg = g_V + (size_t)bh*SEQ*HDIM;

    const int tid = threadIdx.x;
    const int warp = tid >> 5;
    const int lane = tid & 31;
    const int lr = lane >> 2;
    const int lc = lane & 3;

    const int lrow = tid >> 4;
    const int lc4  = (tid & 15) << 2;

    // ---- Stage Q through Vb; issue K0 into Kb[0] concurrently ----
    #pragma unroll
    for (int i = 0; i < 8; i++) {
        const int r = lrow + i*8;
        *(float4*)&Vb[r*FS + lc4] = *(const float4*)(Qg + r*HDIM + lc4);
        cp_async16(&Kb[0][r*FS + lc4], Kg + r*HDIM + lc4);
    }
    CP_COMMIT();                               // G: K_0
    if (tid < 64)
        msk[tid] = (amask[b*SEQ + tid] == 0) ? -INFINITY : 0.0f;
    __syncthreads();

    unsigned qa[8][4];
    #pragma unroll
    for (int ks = 0; ks < 8; ks++) {
        const int row = warp*16 + lr;
        const int kk = ks*8 + lc;
        qa[ks][0] = __float_as_uint(Vb[ row   *FS + kk  ]);
        qa[ks][1] = __float_as_uint(Vb[(row+8)*FS + kk  ]);
        qa[ks][2] = __float_as_uint(Vb[ row   *FS + kk+4]);
        qa[ks][3] = __float_as_uint(Vb[(row+8)*FS + kk+4]);
    }
    // (tile-0 top __syncthreads below certifies Q-extract done before V0 overwrites Vb)

    float m0 = -INFINITY, m1 = -INFINITY, l0 = 0.0f, l1 = 0.0f;
    float o[8][4];
    #pragma unroll
    for (int nt = 0; nt < 8; nt++)
        #pragma unroll
        for (int q = 0; q < 4; q++) o[nt][q] = 0.0f;

    const int r0g = qt*64 + warp*16 + lr;
    const int r1g = r0g + 8;

    for (int kt = 0; kt <= qt; kt++) {
        const int cur = kt & 1;
        float* Ksc = Kb[cur];

        CP_WAIT0();        // K_kt arrived (sole pending group)
        __syncthreads();   // visibility; prior-iter reads of Vb / Kb[cur^1] done

        // issue V_kt (group V), then K_{kt+1} clamped (group K)
        {
            const int kn = (kt < qt) ? kt + 1 : qt;
            #pragma unroll
            for (int i = 0; i < 8; i++) {
                const int r = lrow + i*8;
                cp_async16(&Vb[r*FS + lc4], Vg + (kt*64 + r)*HDIM + lc4);
            }
            CP_COMMIT();
            #pragma unroll
            for (int i = 0; i < 8; i++) {
                const int r = lrow + i*8;
                cp_async16(&Kb[cur^1][r*FS + lc4], Kg + (kn*64 + r)*HDIM + lc4);
            }
            CP_COMMIT();
            if (tid < 64 && kt < qt)
                msk[(cur^1)*64 + tid] =
                    (amask[b*SEQ + (kt+1)*64 + tid] == 0) ? -INFINITY : 0.0f;
        }

        // ---- S = Q @ K^T ----
        float s[8][4];
        #pragma unroll
        for (int nt = 0; nt < 8; nt++)
            #pragma unroll
            for (int q = 0; q < 4; q++) s[nt][q] = 0.0f;

        #pragma unroll
        for (int ks = 0; ks < 8; ks++) {
            #pragma unroll
            for (int nt = 0; nt < 8; nt++) {
                unsigned kb[2];
                kb[0] = __float_as_uint(Ksc[(nt*8 + lr)*FS + ks*8 + lc    ]);
                kb[1] = __float_as_uint(Ksc[(nt*8 + lr)*FS + ks*8 + lc + 4]);
                mma_tf32(s[nt], qa[ks], kb);
            }
        }

        // ---- exp2-domain softmax: logits scaled by 0.125*log2e ----
        const bool diag = (kt == qt);
        float mx0 = -INFINITY, mx1 = -INFINITY;
        #pragma unroll
        for (int nt = 0; nt < 8; nt++) {
            #pragma unroll
            for (int cc = 0; cc < 2; cc++) {
                const int lcol = nt*8 + 2*lc + cc;
                const float ma = msk[cur*64 + lcol];
                float v0 = fmaf(s[nt][cc  ], SCL2, ma);
                float v1 = fmaf(s[nt][cc+2], SCL2, ma);
                if (diag) {
                    const int col = kt*64 + lcol;
                    if (col > r0g) v0 = -3.402823466e38f;
                    if (col > r1g) v1 = -3.402823466e38f;
                }
                s[nt][cc  ] = v0;
                s[nt][cc+2] = v1;
                mx0 = fmaxf(mx0, v0);
                mx1 = fmaxf(mx1, v1);
            }
        }
        mx0 = fmaxf(mx0, __shfl_xor_sync(0xffffffffu, mx0, 1));
        mx0 = fmaxf(mx0, __shfl_xor_sync(0xffffffffu, mx0, 2));
        mx1 = fmaxf(mx1, __shfl_xor_sync(0xffffffffu, mx1, 1));
        mx1 = fmaxf(mx1, __shfl_xor_sync(0xffffffffu, mx1, 2));

        const float mn0 = fmaxf(m0, mx0);
        const float mn1 = fmaxf(m1, mx1);
        const float al0 = exp2f(m0 - mn0);
        const float al1 = exp2f(m1 - mn1);
        float sum0 = 0.0f, sum1 = 0.0f;
        #pragma unroll
        for (int nt = 0; nt < 8; nt++) {
            #pragma unroll
            for (int cc = 0; cc < 2; cc++) {
                const float p0 = tf32r(exp2f(s[nt][cc  ] - mn0));
                const float p1 = tf32r(exp2f(s[nt][cc+2] - mn1));
                s[nt][cc  ] = p0;
                s[nt][cc+2] = p1;
                sum0 += p0;
                sum1 += p1;
            }
        }
        sum0 += __shfl_xor_sync(0xffffffffu, sum0, 1);
        sum0 += __shfl_xor_sync(0xffffffffu, sum0, 2);
        sum1 += __shfl_xor_sync(0xffffffffu, sum1, 1);
        sum1 += __shfl_xor_sync(0xffffffffu, sum1, 2);
        l0 = l0*al0 + sum0;  m0 = mn0;
        l1 = l1*al1 + sum1;  m1 = mn1;
        #pragma unroll
        for (int nt = 0; nt < 8; nt++) {
            o[nt][0] *= al0; o[nt][1] *= al0;
            o[nt][2] *= al1; o[nt][3] *= al1;
        }

        // ---- V_kt must be resident & visible before PV ----
        CP_WAIT1();        // V_kt done; K_next may still fly
        __syncthreads();

        // ---- O += P @ V; P transposed in registers via shuffles ----
        {
            const int src0 = lr*4 + (lc >> 1);
            const int src1 = src0 + 2;
            const bool odd = lc & 1;
            #pragma unroll
            for (int ks = 0; ks < 8; ks++) {
                const float e0 = __shfl_sync(0xffffffffu, s[ks][0], src0);
                const float e1 = __shfl_sync(0xffffffffu, s[ks][1], src0);
                const float f0 = __shfl_sync(0xffffffffu, s[ks][2], src0);
                const float f1 = __shfl_sync(0xffffffffu, s[ks][3], src0);
                const float g0 = __shfl_sync(0xffffffffu, s[ks][0], src1);
                const float g1 = __shfl_sync(0xffffffffu, s[ks][1], src1);
                const float h0 = __shfl_sync(0xffffffffu, s[ks][2], src1);
                const float h1 = __shfl_sync(0xffffffffu, s[ks][3], src1);
                unsigned pa[4];
                pa[0] = __float_as_uint(odd ? e1 : e0);
                pa[1] = __float_as_uint(odd ? f1 : f0);
                pa[2] = __float_as_uint(odd ? g1 : g0);
                pa[3] = __float_as_uint(odd ? h1 : h0);
                #pragma unroll
                for (int nt = 0; nt < 8; nt++) {
                    unsigned vb[2];
                    vb[0] = __float_as_uint(Vb[(ks*8 + lc    )*FS + nt*8 + lr]);
                    vb[1] = __float_as_uint(Vb[(ks*8 + lc + 4)*FS + nt*8 + lr]);
                    mma_tf32(o[nt], pa, vb);
                }
            }
        }
    }
    CP_WAIT0();   // drain trailing K prefetch before exit

    // ---- epilogue ----
    const float inv0 = 1.0f / l0;
    const float inv1 = 1.0f / l1;
    #pragma unroll
    for (int nt = 0; nt < 8; nt++) {
        const int col = h*HDIM + nt*8 + 2*lc;
        float2 v0, v1;
        v0.x = tf32r(o[nt][0]*inv0); v0.y = tf32r(o[nt][1]*inv0);
        v1.x = tf32r(o[nt][2]*inv1); v1.y = tf32r(o[nt][3]*inv1);
        *(float2*)&g_attn[((size_t)b*SEQ + r0g)*CDIM + col] = v0;
        *(float2*)&g_attn[((size_t)b*SEQ + r1g)*CDIM + col] = v1;
    }
}

// ---------------------------------------------------------------------------
// Kernel 3: proj GEMM (unchanged from round 9)
// ---------------------------------------------------------------------------
#define PAS_SZ (64*36)
#define PBS_SZ (32*136)

__global__ __launch_bounds__(256, 3) void proj_gemm_kernel(
    const float* __restrict__ bias,
    float* __restrict__ out)
{
    extern __shared__ __align__(16) float ds[];
    float* Asb[2] = { ds, ds + PAS_SZ };
    float* Bsb[2] = { ds + 2*PAS_SZ, ds + 2*PAS_SZ + PBS_SZ };

    const int tid = threadIdx.x;
    const int bn = blockIdx.x;
    const int bm = blockIdx.y;
    const int warp = tid >> 5;
    const int lane = tid & 31;
    const int wm = warp >> 2;
    const int wn = warp & 3;
    const int lr = lane >> 2;
    const int lc = lane & 3;

    float acc[2][4][4];
    #pragma unroll
    for (int mi = 0; mi < 2; mi++)
        #pragma unroll
        for (int ni = 0; ni < 4; ni++)
            #pragma unroll
            for (int q = 0; q < 4; q++) acc[mi][ni][q] = 0.0f;

    const int arow = tid >> 3;
    const int ac4  = (tid & 7) << 2;
    const int brow = tid >> 5;
    const int bc4  = (tid & 31) << 2;

    const float* Ag = g_attn + (size_t)(bm*64)*CDIM;
    const float* Bg = g_Wpc + bn*128;

    #pragma unroll
    for (int i = 0; i < 2; i++) {
        const int r = arow + i*32;
        cp_async16(&Asb[0][r*36 + ac4], Ag + (size_t)r*CDIM + ac4);
    }
    #pragma unroll
    for (int i = 0; i < 4; i++) {
        const int r = brow + i*8;
        cp_async16(&Bsb[0][r*136 + bc4], Bg + (size_t)r*CDIM + bc4);
    }
    CP_COMMIT();

    for (int it = 0; it < CDIM/32; it++) {
        const int cur = it & 1;
        CP_WAIT0();
        __syncthreads();

        if (it + 1 < CDIM/32) {
            const int k0 = (it+1)*32;
            #pragma unroll
            for (int i = 0; i < 2; i++) {
                const int r = arow + i*32;
                cp_async16(&Asb[cur^1][r*36 + ac4], Ag + (size_t)r*CDIM + k0 + ac4);
            }
            #pragma unroll
            for (int i = 0; i < 4; i++) {
                const int r = brow + i*8;
                cp_async16(&Bsb[cur^1][r*136 + bc4], Bg + (size_t)(k0 + r)*CDIM + bc4);
            }
            CP_COMMIT();
        }

        const float* As = Asb[cur];
        const float* Bs = Bsb[cur];
        #pragma unroll
        for (int ks = 0; ks < 4; ks++) {
            unsigned a[2][4], b[4][2];
            const int kk = ks*8 + lc;
            #pragma unroll
            for (int mi = 0; mi < 2; mi++) {
                const int row = wm*32 + mi*16 + lr;
                a[mi][0] = __float_as_uint(As[ row   *36 + kk  ]);
                a[mi][1] = __float_as_uint(As[(row+8)*36 + kk  ]);
                a[mi][2] = __float_as_uint(As[ row   *36 + kk+4]);
                a[mi][3] = __float_as_uint(As[(row+8)*36 + kk+4]);
            }
            #pragma unroll
            for (int ni = 0; ni < 4; ni++) {
                const int coln = wn*32 + ni*8 + lr;
                b[ni][0] = __float_as_uint(Bs[(ks*8 + lc    )*136 + coln]);
                b[ni][1] = __float_as_uint(Bs[(ks*8 + lc + 4)*136 + coln]);
            }
            #pragma unroll
            for (int mi = 0; mi < 2; mi++)
                #pragma unroll
                for (int ni = 0; ni < 4; ni++)
                    mma_tf32(acc[mi][ni], a[mi], b[ni]);
        }
        __syncthreads();
    }

    #pragma unroll
    for (int mi = 0; mi < 2; mi++) {
        const int r0 = bm*64 + wm*32 + mi*16 + lr;
        const int r1 = r0 + 8;
        #pragma unroll
        for (int ni = 0; ni < 4; ni++) {
            const int n = bn*128 + wn*32 + ni*8 + 2*lc;
            const float b0 = bias[n], b1 = bias[n+1];
            float2 v0, v1;
            v0.x = acc[mi][ni][0] + b0; v0.y = acc[mi][ni][1] + b1;
            v1.x = acc[mi][ni][2] + b0; v1.y = acc[mi][ni][3] + b1;
            *(float2*)&out[(size_t)r0*CDIM + n] = v0;
            *(float2*)&out[(size_t)r1*CDIM + n] = v1;
        }
    }
}

// ---------------------------------------------------------------------------
extern "C" void kernel_launch(void* const* d_in, const int* in_sizes, int n_in,
                              void* d_out, int out_size)
{
    (void)in_sizes; (void)n_in; (void)out_size;
    const float* x      = (const float*)d_in[0];
    const int*   amask  = (const int*)d_in[1];
    const float* W_attn = (const float*)d_in[2];
    const float* b_attn = (const float*)d_in[3];
    const float* W_proj = (const float*)d_in[4];
    const float* b_proj = (const float*)d_in[5];
    float* out = (float*)d_out;

    const int qkv_smem = (2*AS_SZ + 2*BS_SZ) * (int)sizeof(float);    // 71680 B
    cudaFuncSetAttribute(qkv_gemm_kernel,
                         cudaFuncAttributeMaxDynamicSharedMemorySize, qkv_smem);
    const int proj_smem = (2*PAS_SZ + 2*PBS_SZ) * (int)sizeof(float); // 53248 B
    cudaFuncSetAttribute(proj_gemm_kernel,
                         cudaFuncAttributeMaxDynamicSharedMemorySize, proj_smem);
    const int flash_smem = (3*KST + 128) * (int)sizeof(float);        // 52736 B
    cudaFuncSetAttribute(flash_kernel,
                         cudaFuncAttributeMaxDynamicSharedMemorySize, flash_smem);

    prep_tf32_kernel<<<2048, 256>>>(x, W_attn, W_proj);

    {
        dim3 grid(N3/128, MROWS/128);    // (18, 32)
        qkv_gemm_kernel<<<grid, 256, qkv_smem>>>(b_attn);
    }
    {
        dim3 grid(SEQ/64, BHN);          // (32, 24)
        flash_kernel<<<grid, 128, flash_smem>>>(amask);
    }
    {
        dim3 grid(CDIM/128, MROWS/64);   // (6, 64) = 384 blocks
        proj_gemm_kernel<<<grid, 256, proj_smem>>>(b_proj, out);
    }
}

// round 12
// speedup vs baseline: 1.0111x; 1.0111x over previous
#include <cuda_runtime.h>
#include <math.h>
#include <float.h>

// Problem constants
#define BATCH 2
#define SEQ   2048
#define CDIM  768
#define NHEAD 12
#define HDIM  64
#define MROWS (BATCH*SEQ)     // 4096
#define N3    (3*CDIM)        // 2304
#define BHN   (BATCH*NHEAD)   // 24

// Scratch (device globals; no allocation allowed)
__device__ float g_Q[BATCH*NHEAD*SEQ*HDIM];
__device__ float g_K[BATCH*NHEAD*SEQ*HDIM];
__device__ float g_V[BATCH*NHEAD*SEQ*HDIM];
__device__ float g_attn[BATCH*SEQ*CDIM];

// ---------------------------------------------------------------------------
// helpers
// ---------------------------------------------------------------------------
__device__ __forceinline__ float tf32r(float x) {
    unsigned u;
    asm("cvt.rna.tf32.f32 %0, %1;" : "=r"(u) : "f"(x));
    return __uint_as_float(u);
}
__device__ __forceinline__ unsigned tf32u(float x) {
    unsigned u;
    asm("cvt.rna.tf32.f32 %0, %1;" : "=r"(u) : "f"(x));
    return u;
}

__device__ __forceinline__ void mma_tf32(float* c, const unsigned* a, const unsigned* b) {
    asm volatile(
        "mma.sync.aligned.m16n8k8.row.col.f32.tf32.tf32.f32 "
        "{%0,%1,%2,%3},{%4,%5,%6,%7},{%8,%9},{%0,%1,%2,%3};\n"
        : "+f"(c[0]), "+f"(c[1]), "+f"(c[2]), "+f"(c[3])
        : "r"(a[0]), "r"(a[1]), "r"(a[2]), "r"(a[3]), "r"(b[0]), "r"(b[1]));
}

__device__ __forceinline__ void cp_async16(float* smem_dst, const float* gmem_src) {
    unsigned saddr = (unsigned)__cvta_generic_to_shared(smem_dst);
    asm volatile("cp.async.cg.shared.global [%0], [%1], 16;\n"
                 :: "r"(saddr), "l"(gmem_src));
}
#define CP_COMMIT() asm volatile("cp.async.commit_group;\n" ::: "memory")
#define CP_WAIT0()  asm volatile("cp.async.wait_group 0;\n" ::: "memory")

// ---------------------------------------------------------------------------
// Kernel 1: QKV GEMM  [4096,768] @ [768,2304] + bias, scatter into Q/K/V
// cp.async double-buffered; raw fp32 operands, tf32 cvt in fragment build
// ---------------------------------------------------------------------------
#define AS_SZ (128*36)
#define BS_SZ (32*136)

__global__ __launch_bounds__(256, 2) void qkv_gemm_kernel(
    const float* __restrict__ A,      // x [4096,768] raw fp32
    const float* __restrict__ W,      // [768,2304] raw fp32
    const float* __restrict__ bias)   // [2304]
{
    extern __shared__ __align__(16) float ds[];
    float* Asb[2] = { ds, ds + AS_SZ };
    float* Bsb[2] = { ds + 2*AS_SZ, ds + 2*AS_SZ + BS_SZ };

    const int tid = threadIdx.x;
    const int bn = blockIdx.x;
    const int bm = blockIdx.y;
    const int warp = tid >> 5;
    const int lane = tid & 31;
    const int wm = warp >> 2;
    const int wn = warp & 3;
    const int lr = lane >> 2;
    const int lc = lane & 3;

    float acc[4][4][4];
    #pragma unroll
    for (int mi = 0; mi < 4; mi++)
        #pragma unroll
        for (int ni = 0; ni < 4; ni++)
            #pragma unroll
            for (int q = 0; q < 4; q++) acc[mi][ni][q] = 0.0f;

    const int arow = tid >> 3;
    const int ac4  = (tid & 7) << 2;
    const int brow = tid >> 5;
    const int bc4  = (tid & 31) << 2;

    const float* Ag = A + (size_t)(bm*128)*CDIM;
    const float* Bg = W + bn*128;

    #pragma unroll
    for (int i = 0; i < 4; i++) {
        const int r = arow + i*32;
        cp_async16(&Asb[0][r*36 + ac4], Ag + (size_t)r*CDIM + ac4);
    }
    #pragma unroll
    for (int i = 0; i < 4; i++) {
        const int r = brow + i*8;
        cp_async16(&Bsb[0][r*136 + bc4], Bg + (size_t)r*N3 + bc4);
    }
    CP_COMMIT();

    for (int it = 0; it < CDIM/32; it++) {
        const int cur = it & 1;
        CP_WAIT0();
        __syncthreads();

        if (it + 1 < CDIM/32) {
            const int k0 = (it+1)*32;
            #pragma unroll
            for (int i = 0; i < 4; i++) {
                const int r = arow + i*32;
                cp_async16(&Asb[cur^1][r*36 + ac4], Ag + (size_t)r*CDIM + k0 + ac4);
            }
            #pragma unroll
            for (int i = 0; i < 4; i++) {
                const int r = brow + i*8;
                cp_async16(&Bsb[cur^1][r*136 + bc4], Bg + (size_t)(k0 + r)*N3 + bc4);
            }
            CP_COMMIT();
        }

        const float* As = Asb[cur];
        const float* Bs = Bsb[cur];
        #pragma unroll
        for (int ks = 0; ks < 4; ks++) {
            unsigned a[4][4], b[4][2];
            const int kk = ks*8 + lc;
            #pragma unroll
            for (int mi = 0; mi < 4; mi++) {
                const int row = wm*64 + mi*16 + lr;
                a[mi][0] = tf32u(As[ row   *36 + kk  ]);
                a[mi][1] = tf32u(As[(row+8)*36 + kk  ]);
                a[mi][2] = tf32u(As[ row   *36 + kk+4]);
                a[mi][3] = tf32u(As[(row+8)*36 + kk+4]);
            }
            #pragma unroll
            for (int ni = 0; ni < 4; ni++) {
                const int coln = wn*32 + ni*8 + lr;
                b[ni][0] = tf32u(Bs[(ks*8 + lc    )*136 + coln]);
                b[ni][1] = tf32u(Bs[(ks*8 + lc + 4)*136 + coln]);
            }
            #pragma unroll
            for (int mi = 0; mi < 4; mi++)
                #pragma unroll
                for (int ni = 0; ni < 4; ni++)
                    mma_tf32(acc[mi][ni], a[mi], b[ni]);
        }
        __syncthreads();
    }

    #pragma unroll
    for (int mi = 0; mi < 4; mi++) {
        const int r0 = bm*128 + wm*64 + mi*16 + lr;
        const int r1 = r0 + 8;
        #pragma unroll
        for (int ni = 0; ni < 4; ni++) {
            const int n = bn*128 + wn*32 + ni*8 + 2*lc;
            const float b0 = bias[n], b1 = bias[n+1];
            const int part = n / CDIM;
            const int rr = n % CDIM;
            const int h = rr >> 6;
            const int d = rr & 63;
            float* dst = (part == 0) ? g_Q : (part == 1) ? g_K : g_V;
            {
                const int bb = r0 >> 11, t = r0 & 2047;
                float2 v;
                v.x = tf32r(acc[mi][ni][0] + b0);
                v.y = tf32r(acc[mi][ni][1] + b1);
                *(float2*)&dst[(((size_t)bb*NHEAD + h)*SEQ + t)*HDIM + d] = v;
            }
            {
                const int bb = r1 >> 11, t = r1 & 2047;
                float2 v;
                v.x = tf32r(acc[mi][ni][2] + b0);
                v.y = tf32r(acc[mi][ni][3] + b1);
                *(float2*)&dst[(((size_t)bb*NHEAD + h)*SEQ + t)*HDIM + d] = v;
            }
        }
    }
}

// ---------------------------------------------------------------------------
// Kernel 2: flash attention (round-9 version, byte-identical)
// ---------------------------------------------------------------------------
#define FS 68
#define KST (64*FS)

__global__ __launch_bounds__(128, 3) void flash_kernel(const int* __restrict__ amask)
{
    extern __shared__ __align__(16) float dsm[];
    float* Kb0 = dsm;
    float* Kb1 = dsm + KST;
    float* Vb0 = dsm + 2*KST;
    float* Vb1 = dsm + 3*KST;
    float* msk = dsm + 4*KST;

    const int qt = 31 - blockIdx.x;
    const int bh = blockIdx.y;
    const int b  = bh / NHEAD;
    const int h  = bh % NHEAD;

    const float* Qg = g_Q + (size_t)bh*SEQ*HDIM + qt*64*HDIM;
    const float* Kg = g_K + (size_t)bh*SEQ*HDIM;
    const float* Vg = g_V + (size_t)bh*SEQ*HDIM;

    const int tid = threadIdx.x;
    const int warp = tid >> 5;
    const int lane = tid & 31;
    const int lr = lane >> 2;
    const int lc = lane & 3;

    const int lrow = tid >> 4;
    const int lc4  = (tid & 15) << 2;

    #pragma unroll
    for (int i = 0; i < 8; i++) {
        const int r = lrow + i*8;
        *(float4*)&Kb0[r*FS + lc4] = *(const float4*)(Qg + r*HDIM + lc4);
    }
    __syncthreads();

    unsigned qa[8][4];
    #pragma unroll
    for (int ks = 0; ks < 8; ks++) {
        const int row = warp*16 + lr;
        const int kk = ks*8 + lc;
        qa[ks][0] = __float_as_uint(Kb0[ row   *FS + kk  ]);
        qa[ks][1] = __float_as_uint(Kb0[(row+8)*FS + kk  ]);
        qa[ks][2] = __float_as_uint(Kb0[ row   *FS + kk+4]);
        qa[ks][3] = __float_as_uint(Kb0[(row+8)*FS + kk+4]);
    }
    __syncthreads();

    #pragma unroll
    for (int i = 0; i < 8; i++) {
        const int r = lrow + i*8;
        cp_async16(&Kb0[r*FS + lc4], Kg + r*HDIM + lc4);
        cp_async16(&Vb0[r*FS + lc4], Vg + r*HDIM + lc4);
    }
    CP_COMMIT();
    if (tid < 64)
        msk[tid] = (amask[b*SEQ + tid] == 0) ? -INFINITY : 0.0f;

    float m0 = -INFINITY, m1 = -INFINITY, l0 = 0.0f, l1 = 0.0f;
    float o[8][4];
    #pragma unroll
    for (int nt = 0; nt < 8; nt++)
        #pragma unroll
        for (int q = 0; q < 4; q++) o[nt][q] = 0.0f;

    const int r0g = qt*64 + warp*16 + lr;
    const int r1g = r0g + 8;

    for (int kt = 0; kt <= qt; kt++) {
        const int cur = kt & 1;
        float* Ksc = cur ? Kb1 : Kb0;
        float* Vsc = cur ? Vb1 : Vb0;

        CP_WAIT0();
        __syncthreads();

        if (kt < qt) {
            float* Knx = cur ? Kb0 : Kb1;
            float* Vnx = cur ? Vb0 : Vb1;
            #pragma unroll
            for (int i = 0; i < 8; i++) {
                const int r = lrow + i*8;
                cp_async16(&Knx[r*FS + lc4], Kg + ((kt+1)*64 + r)*HDIM + lc4);
                cp_async16(&Vnx[r*FS + lc4], Vg + ((kt+1)*64 + r)*HDIM + lc4);
            }
            CP_COMMIT();
            if (tid < 64)
                msk[(cur^1)*64 + tid] =
                    (amask[b*SEQ + (kt+1)*64 + tid] == 0) ? -INFINITY : 0.0f;
        }

        float s[8][4];
        #pragma unroll
        for (int nt = 0; nt < 8; nt++)
            #pragma unroll
            for (int q = 0; q < 4; q++) s[nt][q] = 0.0f;

        #pragma unroll
        for (int ks = 0; ks < 8; ks++) {
            #pragma unroll
            for (int nt = 0; nt < 8; nt++) {
                unsigned kb[2];
                kb[0] = __float_as_uint(Ksc[(nt*8 + lr)*FS + ks*8 + lc    ]);
                kb[1] = __float_as_uint(Ksc[(nt*8 + lr)*FS + ks*8 + lc + 4]);
                mma_tf32(s[nt], qa[ks], kb);
            }
        }

        const bool diag = (kt == qt);
        float mx0 = -INFINITY, mx1 = -INFINITY;
        #pragma unroll
        for (int nt = 0; nt < 8; nt++) {
            #pragma unroll
            for (int cc = 0; cc < 2; cc++) {
                const int lcol = nt*8 + 2*lc + cc;
                const float ma = msk[cur*64 + lcol];
                float v0 = s[nt][cc  ]*0.125f + ma;
                float v1 = s[nt][cc+2]*0.125f + ma;
                if (diag) {
                    const int col = kt*64 + lcol;
                    if (col > r0g) v0 = -3.402823466e38f;
                    if (col > r1g) v1 = -3.402823466e38f;
                }
                s[nt][cc  ] = v0;
                s[nt][cc+2] = v1;
                mx0 = fmaxf(mx0, v0);
                mx1 = fmaxf(mx1, v1);
            }
        }
        mx0 = fmaxf(mx0, __shfl_xor_sync(0xffffffffu, mx0, 1));
        mx0 = fmaxf(mx0, __shfl_xor_sync(0xffffffffu, mx0, 2));
        mx1 = fmaxf(mx1, __shfl_xor_sync(0xffffffffu, mx1, 1));
        mx1 = fmaxf(mx1, __shfl_xor_sync(0xffffffffu, mx1, 2));

        const float mn0 = fmaxf(m0, mx0);
        const float mn1 = fmaxf(m1, mx1);
        const float al0 = __expf(m0 - mn0);
        const float al1 = __expf(m1 - mn1);
        float sum0 = 0.0f, sum1 = 0.0f;
        #pragma unroll
        for (int nt = 0; nt < 8; nt++) {
            #pragma unroll
            for (int cc = 0; cc < 2; cc++) {
                const float p0 = tf32r(__expf(s[nt][cc  ] - mn0));
                const float p1 = tf32r(__expf(s[nt][cc+2] - mn1));
                s[nt][cc  ] = p0;
                s[nt][cc+2] = p1;
                sum0 += p0;
                sum1 += p1;
            }
        }
        sum0 += __shfl_xor_sync(0xffffffffu, sum0, 1);
        sum0 += __shfl_xor_sync(0xffffffffu, sum0, 2);
        sum1 += __shfl_xor_sync(0xffffffffu, sum1, 1);
        sum1 += __shfl_xor_sync(0xffffffffu, sum1, 2);
        l0 = l0*al0 + sum0;  m0 = mn0;
        l1 = l1*al1 + sum1;  m1 = mn1;
        #pragma unroll
        for (int nt = 0; nt < 8; nt++) {
            o[nt][0] *= al0; o[nt][1] *= al0;
            o[nt][2] *= al1; o[nt][3] *= al1;
        }

        {
            const int src0 = lr*4 + (lc >> 1);
            const int src1 = src0 + 2;
            const bool odd = lc & 1;
            #pragma unroll
            for (int ks = 0; ks < 8; ks++) {
                const float e0 = __shfl_sync(0xffffffffu, s[ks][0], src0);
                const float e1 = __shfl_sync(0xffffffffu, s[ks][1], src0);
                const float f0 = __shfl_sync(0xffffffffu, s[ks][2], src0);
                const float f1 = __shfl_sync(0xffffffffu, s[ks][3], src0);
                const float g0 = __shfl_sync(0xffffffffu, s[ks][0], src1);
                const float g1 = __shfl_sync(0xffffffffu, s[ks][1], src1);
                const float h0 = __shfl_sync(0xffffffffu, s[ks][2], src1);
                const float h1 = __shfl_sync(0xffffffffu, s[ks][3], src1);
                unsigned pa[4];
                pa[0] = __float_as_uint(odd ? e1 : e0);
                pa[1] = __float_as_uint(odd ? f1 : f0);
                pa[2] = __float_as_uint(odd ? g1 : g0);
                pa[3] = __float_as_uint(odd ? h1 : h0);
                #pragma unroll
                for (int nt = 0; nt < 8; nt++) {
                    unsigned vb[2];
                    vb[0] = __float_as_uint(Vsc[(ks*8 + lc    )*FS + nt*8 + lr]);
                    vb[1] = __float_as_uint(Vsc[(ks*8 + lc + 4)*FS + nt*8 + lr]);
                    mma_tf32(o[nt], pa, vb);
                }
            }
        }
    }

    const float inv0 = 1.0f / l0;
    const float inv1 = 1.0f / l1;
    #pragma unroll
    for (int nt = 0; nt < 8; nt++) {
        const int col = h*HDIM + nt*8 + 2*lc;
        float2 v0, v1;
        v0.x = tf32r(o[nt][0]*inv0); v0.y = tf32r(o[nt][1]*inv0);
        v1.x = tf32r(o[nt][2]*inv1); v1.y = tf32r(o[nt][3]*inv1);
        *(float2*)&g_attn[((size_t)b*SEQ + r0g)*CDIM + col] = v0;
        *(float2*)&g_attn[((size_t)b*SEQ + r1g)*CDIM + col] = v1;
    }
}

// ---------------------------------------------------------------------------
// Kernel 3: proj GEMM [4096,768] @ [768,768] + bias -> out
// 64x128 tiles, raw W_proj with tf32 cvt in B-fragment build
// ---------------------------------------------------------------------------
#define PAS_SZ (64*36)
#define PBS_SZ (32*136)

__global__ __launch_bounds__(256, 3) void proj_gemm_kernel(
    const float* __restrict__ W,      // [768,768] raw fp32
    const float* __restrict__ bias,
    float* __restrict__ out)
{
    extern __shared__ __align__(16) float ds[];
    float* Asb[2] = { ds, ds + PAS_SZ };
    float* Bsb[2] = { ds + 2*PAS_SZ, ds + 2*PAS_SZ + PBS_SZ };

    const int tid = threadIdx.x;
    const int bn = blockIdx.x;
    const int bm = blockIdx.y;
    const int warp = tid >> 5;
    const int lane = tid & 31;
    const int wm = warp >> 2;
    const int wn = warp & 3;
    const int lr = lane >> 2;
    const int lc = lane & 3;

    float acc[2][4][4];
    #pragma unroll
    for (int mi = 0; mi < 2; mi++)
        #pragma unroll
        for (int ni = 0; ni < 4; ni++)
            #pragma unroll
            for (int q = 0; q < 4; q++) acc[mi][ni][q] = 0.0f;

    const int arow = tid >> 3;
    const int ac4  = (tid & 7) << 2;
    const int brow = tid >> 5;
    const int bc4  = (tid & 31) << 2;

    const float* Ag = g_attn + (size_t)(bm*64)*CDIM;   // already tf32-rounded
    const float* Bg = W + bn*128;

    #pragma unroll
    for (int i = 0; i < 2; i++) {
        const int r = arow + i*32;
        cp_async16(&Asb[0][r*36 + ac4], Ag + (size_t)r*CDIM + ac4);
    }
    #pragma unroll
    for (int i = 0; i < 4; i++) {
        const int r = brow + i*8;
        cp_async16(&Bsb[0][r*136 + bc4], Bg + (size_t)r*CDIM + bc4);
    }
    CP_COMMIT();

    for (int it = 0; it < CDIM/32; it++) {
        const int cur = it & 1;
        CP_WAIT0();
        __syncthreads();

        if (it + 1 < CDIM/32) {
            const int k0 = (it+1)*32;
            #pragma unroll
            for (int i = 0; i < 2; i++) {
                const int r = arow + i*32;
                cp_async16(&Asb[cur^1][r*36 + ac4], Ag + (size_t)r*CDIM + k0 + ac4);
            }
            #pragma unroll
            for (int i = 0; i < 4; i++) {
                const int r = brow + i*8;
                cp_async16(&Bsb[cur^1][r*136 + bc4], Bg + (size_t)(k0 + r)*CDIM + bc4);
            }
            CP_COMMIT();
        }

        const float* As = Asb[cur];
        const float* Bs = Bsb[cur];
        #pragma unroll
        for (int ks = 0; ks < 4; ks++) {
            unsigned a[2][4], b[4][2];
            const int kk = ks*8 + lc;
            #pragma unroll
            for (int mi = 0; mi < 2; mi++) {
                const int row = wm*32 + mi*16 + lr;
                a[mi][0] = __float_as_uint(As[ row   *36 + kk  ]);
                a[mi][1] = __float_as_uint(As[(row+8)*36 + kk  ]);
                a[mi][2] = __float_as_uint(As[ row   *36 + kk+4]);
                a[mi][3] = __float_as_uint(As[(row+8)*36 + kk+4]);
            }
            #pragma unroll
            for (int ni = 0; ni < 4; ni++) {
                const int coln = wn*32 + ni*8 + lr;
                b[ni][0] = tf32u(Bs[(ks*8 + lc    )*136 + coln]);
                b[ni][1] = tf32u(Bs[(ks*8 + lc + 4)*136 + coln]);
            }
            #pragma unroll
            for (int mi = 0; mi < 2; mi++)
                #pragma unroll
                for (int ni = 0; ni < 4; ni++)
                    mma_tf32(acc[mi][ni], a[mi], b[ni]);
        }
        __syncthreads();
    }

    #pragma unroll
    for (int mi = 0; mi < 2; mi++) {
        const int r0 = bm*64 + wm*32 + mi*16 + lr;
        const int r1 = r0 + 8;
        #pragma unroll
        for (int ni = 0; ni < 4; ni++) {
            const int n = bn*128 + wn*32 + ni*8 + 2*lc;
            const float b0 = bias[n], b1 = bias[n+1];
            float2 v0, v1;
            v0.x = acc[mi][ni][0] + b0; v0.y = acc[mi][ni][1] + b1;
            v1.x = acc[mi][ni][2] + b0; v1.y = acc[mi][ni][3] + b1;
            *(float2*)&out[(size_t)r0*CDIM + n] = v0;
            *(float2*)&out[(size_t)r1*CDIM + n] = v1;
        }
    }
}

// ---------------------------------------------------------------------------
extern "C" void kernel_launch(void* const* d_in, const int* in_sizes, int n_in,
                              void* d_out, int out_size)
{
    (void)in_sizes; (void)n_in; (void)out_size;
    const float* x      = (const float*)d_in[0];
    const int*   amask  = (const int*)d_in[1];
    const float* W_attn = (const float*)d_in[2];
    const float* b_attn = (const float*)d_in[3];
    const float* W_proj = (const float*)d_in[4];
    const float* b_proj = (const float*)d_in[5];
    float* out = (float*)d_out;

    const int qkv_smem = (2*AS_SZ + 2*BS_SZ) * (int)sizeof(float);    // 71680 B
    cudaFuncSetAttribute(qkv_gemm_kernel,
                         cudaFuncAttributeMaxDynamicSharedMemorySize, qkv_smem);
    const int proj_smem = (2*PAS_SZ + 2*PBS_SZ) * (int)sizeof(float); // 53248 B
    cudaFuncSetAttribute(proj_gemm_kernel,
                         cudaFuncAttributeMaxDynamicSharedMemorySize, proj_smem);
    const int flash_smem = (4*KST + 128) * (int)sizeof(float);        // 70144 B
    cudaFuncSetAttribute(flash_kernel,
                         cudaFuncAttributeMaxDynamicSharedMemorySize, flash_smem);

    {
        dim3 grid(N3/128, MROWS/128);    // (18, 32)
        qkv_gemm_kernel<<<grid, 256, qkv_smem>>>(x, W_attn, b_attn);
    }
    {
        dim3 grid(SEQ/64, BHN);          // (32, 24)
        flash_kernel<<<grid, 128, flash_smem>>>(amask);
    }
    {
        dim3 grid(CDIM/128, MROWS/64);   // (6, 64) = 384 blocks
        proj_gemm_kernel<<<grid, 256, proj_smem>>>(W_proj, b_proj, out);
    }
}

// round 14
// speedup vs baseline: 1.0715x; 1.0597x over previous
#include <cuda_runtime.h>
#include <math.h>
#include <float.h>

// Problem constants
#define BATCH 2
#define SEQ   2048
#define CDIM  768
#define NHEAD 12
#define HDIM  64
#define MROWS (BATCH*SEQ)     // 4096
#define N3    (3*CDIM)        // 2304
#define BHN   (BATCH*NHEAD)   // 24

// Scratch (device globals; no allocation allowed)
__device__ float g_Q[BATCH*NHEAD*SEQ*HDIM];
__device__ float g_K[BATCH*NHEAD*SEQ*HDIM];
__device__ float g_V[BATCH*NHEAD*SEQ*HDIM];
__device__ float g_attn[BATCH*SEQ*CDIM];

// ---------------------------------------------------------------------------
// helpers
// ---------------------------------------------------------------------------
__device__ __forceinline__ float tf32r(float x) {
    unsigned u;
    asm("cvt.rna.tf32.f32 %0, %1;" : "=r"(u) : "f"(x));
    return __uint_as_float(u);
}
__device__ __forceinline__ unsigned tf32u(float x) {
    unsigned u;
    asm("cvt.rna.tf32.f32 %0, %1;" : "=r"(u) : "f"(x));
    return u;
}

__device__ __forceinline__ void mma_tf32(float* c, const unsigned* a, const unsigned* b) {
    asm volatile(
        "mma.sync.aligned.m16n8k8.row.col.f32.tf32.tf32.f32 "
        "{%0,%1,%2,%3},{%4,%5,%6,%7},{%8,%9},{%0,%1,%2,%3};\n"
        : "+f"(c[0]), "+f"(c[1]), "+f"(c[2]), "+f"(c[3])
        : "r"(a[0]), "r"(a[1]), "r"(a[2]), "r"(a[3]), "r"(b[0]), "r"(b[1]));
}

__device__ __forceinline__ void cp_async16(float* smem_dst, const float* gmem_src) {
    unsigned saddr = (unsigned)__cvta_generic_to_shared(smem_dst);
    asm volatile("cp.async.cg.shared.global [%0], [%1], 16;\n"
                 :: "r"(saddr), "l"(gmem_src));
}
#define CP_COMMIT() asm volatile("cp.async.commit_group;\n" ::: "memory")
#define CP_WAIT0()  asm volatile("cp.async.wait_group 0;\n" ::: "memory")

// ---------------------------------------------------------------------------
// Kernel 1: QKV GEMM  [4096,768] @ [768,2304] + bias, scatter into Q/K/V
// Round-4 version: static smem, LDG->cvt->STS (cvt off the MMA-issue path)
// ---------------------------------------------------------------------------
__global__ __launch_bounds__(256, 2) void qkv_gemm_kernel(
    const float* __restrict__ A,      // x [4096,768]
    const float* __restrict__ W,      // [768,2304]
    const float* __restrict__ bias)   // [2304]
{
    __shared__ __align__(16) float As[128][36];
    __shared__ __align__(16) float Bs[32][136];

    const int tid = threadIdx.x;
    const int bn = blockIdx.x;   // 0..17
    const int bm = blockIdx.y;   // 0..31
    const int warp = tid >> 5;
    const int lane = tid & 31;
    const int wm = warp >> 2;
    const int wn = warp & 3;
    const int lr = lane >> 2;
    const int lc = lane & 3;

    float acc[4][4][4];
    #pragma unroll
    for (int mi = 0; mi < 4; mi++)
        #pragma unroll
        for (int ni = 0; ni < 4; ni++)
            #pragma unroll
            for (int q = 0; q < 4; q++) acc[mi][ni][q] = 0.0f;

    const int arow = tid >> 3;
    const int ac4  = (tid & 7) << 2;
    const int brow = tid >> 5;
    const int bc4  = (tid & 31) << 2;

    for (int k0 = 0; k0 < CDIM; k0 += 32) {
        #pragma unroll
        for (int i = 0; i < 4; i++) {
            const int r = arow + i*32;
            float4 v = *(const float4*)(A + (size_t)(bm*128 + r)*CDIM + k0 + ac4);
            float4 t;
            t.x = tf32r(v.x); t.y = tf32r(v.y); t.z = tf32r(v.z); t.w = tf32r(v.w);
            *(float4*)&As[r][ac4] = t;
        }
        #pragma unroll
        for (int i = 0; i < 4; i++) {
            const int r = brow + i*8;
            float4 v = *(const float4*)(W + (size_t)(k0 + r)*N3 + bn*128 + bc4);
            float4 t;
            t.x = tf32r(v.x); t.y = tf32r(v.y); t.z = tf32r(v.z); t.w = tf32r(v.w);
            *(float4*)&Bs[r][bc4] = t;
        }
        __syncthreads();

        #pragma unroll
        for (int ks = 0; ks < 4; ks++) {
            unsigned a[4][4], b[4][2];
            const int kk = ks*8 + lc;
            #pragma unroll
            for (int mi = 0; mi < 4; mi++) {
                const int row = wm*64 + mi*16 + lr;
                a[mi][0] = __float_as_uint(As[row  ][kk  ]);
                a[mi][1] = __float_as_uint(As[row+8][kk  ]);
                a[mi][2] = __float_as_uint(As[row  ][kk+4]);
                a[mi][3] = __float_as_uint(As[row+8][kk+4]);
            }
            #pragma unroll
            for (int ni = 0; ni < 4; ni++) {
                const int coln = wn*32 + ni*8 + lr;
                b[ni][0] = __float_as_uint(Bs[ks*8 + lc    ][coln]);
                b[ni][1] = __float_as_uint(Bs[ks*8 + lc + 4][coln]);
            }
            #pragma unroll
            for (int mi = 0; mi < 4; mi++)
                #pragma unroll
                for (int ni = 0; ni < 4; ni++)
                    mma_tf32(acc[mi][ni], a[mi], b[ni]);
        }
        __syncthreads();
    }

    #pragma unroll
    for (int mi = 0; mi < 4; mi++) {
        const int r0 = bm*128 + wm*64 + mi*16 + lr;
        const int r1 = r0 + 8;
        #pragma unroll
        for (int ni = 0; ni < 4; ni++) {
            const int n = bn*128 + wn*32 + ni*8 + 2*lc;
            const float b0 = bias[n], b1 = bias[n+1];
            const int part = n / CDIM;
            const int rr = n % CDIM;
            const int h = rr >> 6;
            const int d = rr & 63;
            float* dst = (part == 0) ? g_Q : (part == 1) ? g_K : g_V;
            {
                const int bb = r0 >> 11, t = r0 & 2047;
                float2 v;
                v.x = tf32r(acc[mi][ni][0] + b0);
                v.y = tf32r(acc[mi][ni][1] + b1);
                *(float2*)&dst[(((size_t)bb*NHEAD + h)*SEQ + t)*HDIM + d] = v;
            }
            {
                const int bb = r1 >> 11, t = r1 & 2047;
                float2 v;
                v.x = tf32r(acc[mi][ni][2] + b0);
                v.y = tf32r(acc[mi][ni][3] + b1);
                *(float2*)&dst[(((size_t)bb*NHEAD + h)*SEQ + t)*HDIM + d] = v;
            }
        }
    }
}

// ---------------------------------------------------------------------------
// Kernel 2: flash attention (round-9 version, byte-identical)
// ---------------------------------------------------------------------------
#define FS 68
#define KST (64*FS)

__global__ __launch_bounds__(128, 3) void flash_kernel(const int* __restrict__ amask)
{
    extern __shared__ __align__(16) float dsm[];
    float* Kb0 = dsm;
    float* Kb1 = dsm + KST;
    float* Vb0 = dsm + 2*KST;
    float* Vb1 = dsm + 3*KST;
    float* msk = dsm + 4*KST;

    const int qt = 31 - blockIdx.x;
    const int bh = blockIdx.y;
    const int b  = bh / NHEAD;
    const int h  = bh % NHEAD;

    const float* Qg = g_Q + (size_t)bh*SEQ*HDIM + qt*64*HDIM;
    const float* Kg = g_K + (size_t)bh*SEQ*HDIM;
    const float* Vg = g_V + (size_t)bh*SEQ*HDIM;

    const int tid = threadIdx.x;
    const int warp = tid >> 5;
    const int lane = tid & 31;
    const int lr = lane >> 2;
    const int lc = lane & 3;

    const int lrow = tid >> 4;
    const int lc4  = (tid & 15) << 2;

    #pragma unroll
    for (int i = 0; i < 8; i++) {
        const int r = lrow + i*8;
        *(float4*)&Kb0[r*FS + lc4] = *(const float4*)(Qg + r*HDIM + lc4);
    }
    __syncthreads();

    unsigned qa[8][4];
    #pragma unroll
    for (int ks = 0; ks < 8; ks++) {
        const int row = warp*16 + lr;
        const int kk = ks*8 + lc;
        qa[ks][0] = __float_as_uint(Kb0[ row   *FS + kk  ]);
        qa[ks][1] = __float_as_uint(Kb0[(row+8)*FS + kk  ]);
        qa[ks][2] = __float_as_uint(Kb0[ row   *FS + kk+4]);
        qa[ks][3] = __float_as_uint(Kb0[(row+8)*FS + kk+4]);
    }
    __syncthreads();

    #pragma unroll
    for (int i = 0; i < 8; i++) {
        const int r = lrow + i*8;
        cp_async16(&Kb0[r*FS + lc4], Kg + r*HDIM + lc4);
        cp_async16(&Vb0[r*FS + lc4], Vg + r*HDIM + lc4);
    }
    CP_COMMIT();
    if (tid < 64)
        msk[tid] = (amask[b*SEQ + tid] == 0) ? -INFINITY : 0.0f;

    float m0 = -INFINITY, m1 = -INFINITY, l0 = 0.0f, l1 = 0.0f;
    float o[8][4];
    #pragma unroll
    for (int nt = 0; nt < 8; nt++)
        #pragma unroll
        for (int q = 0; q < 4; q++) o[nt][q] = 0.0f;

    const int r0g = qt*64 + warp*16 + lr;
    const int r1g = r0g + 8;

    for (int kt = 0; kt <= qt; kt++) {
        const int cur = kt & 1;
        float* Ksc = cur ? Kb1 : Kb0;
        float* Vsc = cur ? Vb1 : Vb0;

        CP_WAIT0();
        __syncthreads();

        if (kt < qt) {
            float* Knx = cur ? Kb0 : Kb1;
            float* Vnx = cur ? Vb0 : Vb1;
            #pragma unroll
            for (int i = 0; i < 8; i++) {
                const int r = lrow + i*8;
                cp_async16(&Knx[r*FS + lc4], Kg + ((kt+1)*64 + r)*HDIM + lc4);
                cp_async16(&Vnx[r*FS + lc4], Vg + ((kt+1)*64 + r)*HDIM + lc4);
            }
            CP_COMMIT();
            if (tid < 64)
                msk[(cur^1)*64 + tid] =
                    (amask[b*SEQ + (kt+1)*64 + tid] == 0) ? -INFINITY : 0.0f;
        }

        float s[8][4];
        #pragma unroll
        for (int nt = 0; nt < 8; nt++)
            #pragma unroll
            for (int q = 0; q < 4; q++) s[nt][q] = 0.0f;

        #pragma unroll
        for (int ks = 0; ks < 8; ks++) {
            #pragma unroll
            for (int nt = 0; nt < 8; nt++) {
                unsigned kb[2];
                kb[0] = __float_as_uint(Ksc[(nt*8 + lr)*FS + ks*8 + lc    ]);
                kb[1] = __float_as_uint(Ksc[(nt*8 + lr)*FS + ks*8 + lc + 4]);
                mma_tf32(s[nt], qa[ks], kb);
            }
        }

        const bool diag = (kt == qt);
        float mx0 = -INFINITY, mx1 = -INFINITY;
        #pragma unroll
        for (int nt = 0; nt < 8; nt++) {
            #pragma unroll
            for (int cc = 0; cc < 2; cc++) {
                const int lcol = nt*8 + 2*lc + cc;
                const float ma = msk[cur*64 + lcol];
                float v0 = s[nt][cc  ]*0.125f + ma;
                float v1 = s[nt][cc+2]*0.125f + ma;
                if (diag) {
                    const int col = kt*64 + lcol;
                    if (col > r0g) v0 = -3.402823466e38f;
                    if (col > r1g) v1 = -3.402823466e38f;
                }
                s[nt][cc  ] = v0;
                s[nt][cc+2] = v1;
                mx0 = fmaxf(mx0, v0);
                mx1 = fmaxf(mx1, v1);
            }
        }
        mx0 = fmaxf(mx0, __shfl_xor_sync(0xffffffffu, mx0, 1));
        mx0 = fmaxf(mx0, __shfl_xor_sync(0xffffffffu, mx0, 2));
        mx1 = fmaxf(mx1, __shfl_xor_sync(0xffffffffu, mx1, 1));
        mx1 = fmaxf(mx1, __shfl_xor_sync(0xffffffffu, mx1, 2));

        const float mn0 = fmaxf(m0, mx0);
        const float mn1 = fmaxf(m1, mx1);
        const float al0 = __expf(m0 - mn0);
        const float al1 = __expf(m1 - mn1);
        float sum0 = 0.0f, sum1 = 0.0f;
        #pragma unroll
        for (int nt = 0; nt < 8; nt++) {
            #pragma unroll
            for (int cc = 0; cc < 2; cc++) {
                const float p0 = tf32r(__expf(s[nt][cc  ] - mn0));
                const float p1 = tf32r(__expf(s[nt][cc+2] - mn1));
                s[nt][cc  ] = p0;
                s[nt][cc+2] = p1;
                sum0 += p0;
                sum1 += p1;
            }
        }
        sum0 += __shfl_xor_sync(0xffffffffu, sum0, 1);
        sum0 += __shfl_xor_sync(0xffffffffu, sum0, 2);
        sum1 += __shfl_xor_sync(0xffffffffu, sum1, 1);
        sum1 += __shfl_xor_sync(0xffffffffu, sum1, 2);
        l0 = l0*al0 + sum0;  m0 = mn0;
        l1 = l1*al1 + sum1;  m1 = mn1;
        #pragma unroll
        for (int nt = 0; nt < 8; nt++) {
            o[nt][0] *= al0; o[nt][1] *= al0;
            o[nt][2] *= al1; o[nt][3] *= al1;
        }

        {
            const int src0 = lr*4 + (lc >> 1);
            const int src1 = src0 + 2;
            const bool odd = lc & 1;
            #pragma unroll
            for (int ks = 0; ks < 8; ks++) {
                const float e0 = __shfl_sync(0xffffffffu, s[ks][0], src0);
                const float e1 = __shfl_sync(0xffffffffu, s[ks][1], src0);
                const float f0 = __shfl_sync(0xffffffffu, s[ks][2], src0);
                const float f1 = __shfl_sync(0xffffffffu, s[ks][3], src0);
                const float g0 = __shfl_sync(0xffffffffu, s[ks][0], src1);
                const float g1 = __shfl_sync(0xffffffffu, s[ks][1], src1);
                const float h0 = __shfl_sync(0xffffffffu, s[ks][2], src1);
                const float h1 = __shfl_sync(0xffffffffu, s[ks][3], src1);
                unsigned pa[4];
                pa[0] = __float_as_uint(odd ? e1 : e0);
                pa[1] = __float_as_uint(odd ? f1 : f0);
                pa[2] = __float_as_uint(odd ? g1 : g0);
                pa[3] = __float_as_uint(odd ? h1 : h0);
                #pragma unroll
                for (int nt = 0; nt < 8; nt++) {
                    unsigned vb[2];
                    vb[0] = __float_as_uint(Vsc[(ks*8 + lc    )*FS + nt*8 + lr]);
                    vb[1] = __float_as_uint(Vsc[(ks*8 + lc + 4)*FS + nt*8 + lr]);
                    mma_tf32(o[nt], pa, vb);
                }
            }
        }
    }

    const float inv0 = 1.0f / l0;
    const float inv1 = 1.0f / l1;
    #pragma unroll
    for (int nt = 0; nt < 8; nt++) {
        const int col = h*HDIM + nt*8 + 2*lc;
        float2 v0, v1;
        v0.x = tf32r(o[nt][0]*inv0); v0.y = tf32r(o[nt][1]*inv0);
        v1.x = tf32r(o[nt][2]*inv1); v1.y = tf32r(o[nt][3]*inv1);
        *(float2*)&g_attn[((size_t)b*SEQ + r0g)*CDIM + col] = v0;
        *(float2*)&g_attn[((size_t)b*SEQ + r1g)*CDIM + col] = v1;
    }
}

// ---------------------------------------------------------------------------
// Kernel 3: proj GEMM [4096,768] @ [768,768] + bias -> out
// (round-12 version: 64x128 tiles, cp.async, cvt only in B-fragment build)
// ---------------------------------------------------------------------------
#define PAS_SZ (64*36)
#define PBS_SZ (32*136)

__global__ __launch_bounds__(256, 3) void proj_gemm_kernel(
    const float* __restrict__ W,      // [768,768] raw fp32
    const float* __restrict__ bias,
    float* __restrict__ out)
{
    extern __shared__ __align__(16) float ds[];
    float* Asb[2] = { ds, ds + PAS_SZ };
    float* Bsb[2] = { ds + 2*PAS_SZ, ds + 2*PAS_SZ + PBS_SZ };

    const int tid = threadIdx.x;
    const int bn = blockIdx.x;
    const int bm = blockIdx.y;
    const int warp = tid >> 5;
    const int lane = tid & 31;
    const int wm = warp >> 2;
    const int wn = warp & 3;
    const int lr = lane >> 2;
    const int lc = lane & 3;

    float acc[2][4][4];
    #pragma unroll
    for (int mi = 0; mi < 2; mi++)
        #pragma unroll
        for (int ni = 0; ni < 4; ni++)
            #pragma unroll
            for (int q = 0; q < 4; q++) acc[mi][ni][q] = 0.0f;

    const int arow = tid >> 3;
    const int ac4  = (tid & 7) << 2;
    const int brow = tid >> 5;
    const int bc4  = (tid & 31) << 2;

    const float* Ag = g_attn + (size_t)(bm*64)*CDIM;   // already tf32-rounded
    const float* Bg = W + bn*128;

    #pragma unroll
    for (int i = 0; i < 2; i++) {
        const int r = arow + i*32;
        cp_async16(&Asb[0][r*36 + ac4], Ag + (size_t)r*CDIM + ac4);
    }
    #pragma unroll
    for (int i = 0; i < 4; i++) {
        const int r = brow + i*8;
        cp_async16(&Bsb[0][r*136 + bc4], Bg + (size_t)r*CDIM + bc4);
    }
    CP_COMMIT();

    for (int it = 0; it < CDIM/32; it++) {
        const int cur = it & 1;
        CP_WAIT0();
        __syncthreads();

        if (it + 1 < CDIM/32) {
            const int k0 = (it+1)*32;
            #pragma unroll
            for (int i = 0; i < 2; i++) {
                const int r = arow + i*32;
                cp_async16(&Asb[cur^1][r*36 + ac4], Ag + (size_t)r*CDIM + k0 + ac4);
            }
            #pragma unroll
            for (int i = 0; i < 4; i++) {
                const int r = brow + i*8;
                cp_async16(&Bsb[cur^1][r*136 + bc4], Bg + (size_t)(k0 + r)*CDIM + bc4);
            }
            CP_COMMIT();
        }

        const float* As = Asb[cur];
        const float* Bs = Bsb[cur];
        #pragma unroll
        for (int ks = 0; ks < 4; ks++) {
            unsigned a[2][4], b[4][2];
            const int kk = ks*8 + lc;
            #pragma unroll
            for (int mi = 0; mi < 2; mi++) {
                const int row = wm*32 + mi*16 + lr;
                a[mi][0] = __float_as_uint(As[ row   *36 + kk  ]);
                a[mi][1] = __float_as_uint(As[(row+8)*36 + kk  ]);
                a[mi][2] = __float_as_uint(As[ row   *36 + kk+4]);
                a[mi][3] = __float_as_uint(As[(row+8)*36 + kk+4]);
            }
            #pragma unroll
            for (int ni = 0; ni < 4; ni++) {
                const int coln = wn*32 + ni*8 + lr;
                b[ni][0] = tf32u(Bs[(ks*8 + lc    )*136 + coln]);
                b[ni][1] = tf32u(Bs[(ks*8 + lc + 4)*136 + coln]);
            }
            #pragma unroll
            for (int mi = 0; mi < 2; mi++)
                #pragma unroll
                for (int ni = 0; ni < 4; ni++)
                    mma_tf32(acc[mi][ni], a[mi], b[ni]);
        }
        __syncthreads();
    }

    #pragma unroll
    for (int mi = 0; mi < 2; mi++) {
        const int r0 = bm*64 + wm*32 + mi*16 + lr;
        const int r1 = r0 + 8;
        #pragma unroll
        for (int ni = 0; ni < 4; ni++) {
            const int n = bn*128 + wn*32 + ni*8 + 2*lc;
            const float b0 = bias[n], b1 = bias[n+1];
            float2 v0, v1;
            v0.x = acc[mi][ni][0] + b0; v0.y = acc[mi][ni][1] + b1;
            v1.x = acc[mi][ni][2] + b0; v1.y = acc[mi][ni][3] + b1;
            *(float2*)&out[(size_t)r0*CDIM + n] = v0;
            *(float2*)&out[(size_t)r1*CDIM + n] = v1;
        }
    }
}

// ---------------------------------------------------------------------------
extern "C" void kernel_launch(void* const* d_in, const int* in_sizes, int n_in,
                              void* d_out, int out_size)
{
    (void)in_sizes; (void)n_in; (void)out_size;
    const float* x      = (const float*)d_in[0];
    const int*   amask  = (const int*)d_in[1];
    const float* W_attn = (const float*)d_in[2];
    const float* b_attn = (const float*)d_in[3];
    const float* W_proj = (const float*)d_in[4];
    const float* b_proj = (const float*)d_in[5];
    float* out = (float*)d_out;

    const int proj_smem = (2*PAS_SZ + 2*PBS_SZ) * (int)sizeof(float); // 53248 B
    cudaFuncSetAttribute(proj_gemm_kernel,
                         cudaFuncAttributeMaxDynamicSharedMemorySize, proj_smem);
    const int flash_smem = (4*KST + 128) * (int)sizeof(float);        // 70144 B
    cudaFuncSetAttribute(flash_kernel,
                         cudaFuncAttributeMaxDynamicSharedMemorySize, flash_smem);

    {
        dim3 grid(N3/128, MROWS/128);    // (18, 32)
        qkv_gemm_kernel<<<grid, 256>>>(x, W_attn, b_attn);
    }
    {
        dim3 grid(SEQ/64, BHN);          // (32, 24)
        flash_kernel<<<grid, 128, flash_smem>>>(amask);
    }
    {
        dim3 grid(CDIM/128, MROWS/64);   // (6, 64) = 384 blocks
        proj_gemm_kernel<<<grid, 256, proj_smem>>>(W_proj, b_proj, out);
    }
}

// round 15
// speedup vs baseline: 1.1972x; 1.1172x over previous
#include <cuda_runtime.h>
#include <math.h>
#include <float.h>

// Problem constants
#define BATCH 2
#define SEQ   2048
#define CDIM  768
#define NHEAD 12
#define HDIM  64
#define MROWS (BATCH*SEQ)     // 4096
#define N3    (3*CDIM)        // 2304
#define BHN   (BATCH*NHEAD)   // 24

// Scratch (device globals; no allocation allowed)
__device__ float g_Q[BATCH*NHEAD*SEQ*HDIM];
__device__ float g_K[BATCH*NHEAD*SEQ*HDIM];
__device__ float g_V[BATCH*NHEAD*SEQ*HDIM];
__device__ float g_attn[BATCH*SEQ*CDIM];

// ---------------------------------------------------------------------------
// helpers
// ---------------------------------------------------------------------------
__device__ __forceinline__ float tf32r(float x) {
    unsigned u;
    asm("cvt.rna.tf32.f32 %0, %1;" : "=r"(u) : "f"(x));
    return __uint_as_float(u);
}
__device__ __forceinline__ unsigned tf32u(float x) {
    unsigned u;
    asm("cvt.rna.tf32.f32 %0, %1;" : "=r"(u) : "f"(x));
    return u;
}

__device__ __forceinline__ void mma_tf32(float* c, const unsigned* a, const unsigned* b) {
    asm volatile(
        "mma.sync.aligned.m16n8k8.row.col.f32.tf32.tf32.f32 "
        "{%0,%1,%2,%3},{%4,%5,%6,%7},{%8,%9},{%0,%1,%2,%3};\n"
        : "+f"(c[0]), "+f"(c[1]), "+f"(c[2]), "+f"(c[3])
        : "r"(a[0]), "r"(a[1]), "r"(a[2]), "r"(a[3]), "r"(b[0]), "r"(b[1]));
}

__device__ __forceinline__ void cp_async16(float* smem_dst, const float* gmem_src) {
    unsigned saddr = (unsigned)__cvta_generic_to_shared(smem_dst);
    asm volatile("cp.async.cg.shared.global [%0], [%1], 16;\n"
                 :: "r"(saddr), "l"(gmem_src));
}
#define CP_COMMIT() asm volatile("cp.async.commit_group;\n" ::: "memory")
#define CP_WAIT0()  asm volatile("cp.async.wait_group 0;\n" ::: "memory")

// ---------------------------------------------------------------------------
// Kernel 1: QKV GEMM  [4096,768] @ [768,2304] + bias, scatter into Q/K/V
// Round-4 version: static smem, LDG->cvt->STS (cvt off the MMA-issue path)
// ---------------------------------------------------------------------------
__global__ __launch_bounds__(256, 2) void qkv_gemm_kernel(
    const float* __restrict__ A,      // x [4096,768]
    const float* __restrict__ W,      // [768,2304]
    const float* __restrict__ bias)   // [2304]
{
    __shared__ __align__(16) float As[128][36];
    __shared__ __align__(16) float Bs[32][136];

    const int tid = threadIdx.x;
    const int bn = blockIdx.x;   // 0..17
    const int bm = blockIdx.y;   // 0..31
    const int warp = tid >> 5;
    const int lane = tid & 31;
    const int wm = warp >> 2;
    const int wn = warp & 3;
    const int lr = lane >> 2;
    const int lc = lane & 3;

    float acc[4][4][4];
    #pragma unroll
    for (int mi = 0; mi < 4; mi++)
        #pragma unroll
        for (int ni = 0; ni < 4; ni++)
            #pragma unroll
            for (int q = 0; q < 4; q++) acc[mi][ni][q] = 0.0f;

    const int arow = tid >> 3;
    const int ac4  = (tid & 7) << 2;
    const int brow = tid >> 5;
    const int bc4  = (tid & 31) << 2;

    for (int k0 = 0; k0 < CDIM; k0 += 32) {
        #pragma unroll
        for (int i = 0; i < 4; i++) {
            const int r = arow + i*32;
            float4 v = *(const float4*)(A + (size_t)(bm*128 + r)*CDIM + k0 + ac4);
            float4 t;
            t.x = tf32r(v.x); t.y = tf32r(v.y); t.z = tf32r(v.z); t.w = tf32r(v.w);
            *(float4*)&As[r][ac4] = t;
        }
        #pragma unroll
        for (int i = 0; i < 4; i++) {
            const int r = brow + i*8;
            float4 v = *(const float4*)(W + (size_t)(k0 + r)*N3 + bn*128 + bc4);
            float4 t;
            t.x = tf32r(v.x); t.y = tf32r(v.y); t.z = tf32r(v.z); t.w = tf32r(v.w);
            *(float4*)&Bs[r][bc4] = t;
        }
        __syncthreads();

        #pragma unroll
        for (int ks = 0; ks < 4; ks++) {
            unsigned a[4][4], b[4][2];
            const int kk = ks*8 + lc;
            #pragma unroll
            for (int mi = 0; mi < 4; mi++) {
                const int row = wm*64 + mi*16 + lr;
                a[mi][0] = __float_as_uint(As[row  ][kk  ]);
                a[mi][1] = __float_as_uint(As[row+8][kk  ]);
                a[mi][2] = __float_as_uint(As[row  ][kk+4]);
                a[mi][3] = __float_as_uint(As[row+8][kk+4]);
            }
            #pragma unroll
            for (int ni = 0; ni < 4; ni++) {
                const int coln = wn*32 + ni*8 + lr;
                b[ni][0] = __float_as_uint(Bs[ks*8 + lc    ][coln]);
                b[ni][1] = __float_as_uint(Bs[ks*8 + lc + 4][coln]);
            }
            #pragma unroll
            for (int mi = 0; mi < 4; mi++)
                #pragma unroll
                for (int ni = 0; ni < 4; ni++)
                    mma_tf32(acc[mi][ni], a[mi], b[ni]);
        }
        __syncthreads();
    }

    #pragma unroll
    for (int mi = 0; mi < 4; mi++) {
        const int r0 = bm*128 + wm*64 + mi*16 + lr;
        const int r1 = r0 + 8;
        #pragma unroll
        for (int ni = 0; ni < 4; ni++) {
            const int n = bn*128 + wn*32 + ni*8 + 2*lc;
            const float b0 = bias[n], b1 = bias[n+1];
            const int part = n / CDIM;
            const int rr = n % CDIM;
            const int h = rr >> 6;
            const int d = rr & 63;
            float* dst = (part == 0) ? g_Q : (part == 1) ? g_K : g_V;
            {
                const int bb = r0 >> 11, t = r0 & 2047;
                float2 v;
                v.x = tf32r(acc[mi][ni][0] + b0);
                v.y = tf32r(acc[mi][ni][1] + b1);
                *(float2*)&dst[(((size_t)bb*NHEAD + h)*SEQ + t)*HDIM + d] = v;
            }
            {
                const int bb = r1 >> 11, t = r1 & 2047;
                float2 v;
                v.x = tf32r(acc[mi][ni][2] + b0);
                v.y = tf32r(acc[mi][ni][3] + b1);
                *(float2*)&dst[(((size_t)bb*NHEAD + h)*SEQ + t)*HDIM + d] = v;
            }
        }
    }
}

// ---------------------------------------------------------------------------
// Kernel 2: flash attention (round-9 body; grid axes swapped for GLOBAL
// heavy-first scheduling: bh on x, qt on y -> all qt=31 blocks launch first)
// ---------------------------------------------------------------------------
#define FS 68
#define KST (64*FS)

__global__ __launch_bounds__(128, 3) void flash_kernel(const int* __restrict__ amask)
{
    extern __shared__ __align__(16) float dsm[];
    float* Kb0 = dsm;
    float* Kb1 = dsm + KST;
    float* Vb0 = dsm + 2*KST;
    float* Vb1 = dsm + 3*KST;
    float* msk = dsm + 4*KST;

    const int bh = blockIdx.x;       // 0..23  (fastest axis)
    const int qt = 31 - blockIdx.y;  // heavy-first globally
    const int b  = bh / NHEAD;
    const int h  = bh % NHEAD;

    const float* Qg = g_Q + (size_t)bh*SEQ*HDIM + qt*64*HDIM;
    const float* Kg = g_K + (size_t)bh*SEQ*HDIM;
    const float* Vg = g_V + (size_t)bh*SEQ*HDIM;

    const int tid = threadIdx.x;
    const int warp = tid >> 5;
    const int lane = tid & 31;
    const int lr = lane >> 2;
    const int lc = lane & 3;

    const int lrow = tid >> 4;
    const int lc4  = (tid & 15) << 2;

    #pragma unroll
    for (int i = 0; i < 8; i++) {
        const int r = lrow + i*8;
        *(float4*)&Kb0[r*FS + lc4] = *(const float4*)(Qg + r*HDIM + lc4);
    }
    __syncthreads();

    unsigned qa[8][4];
    #pragma unroll
    for (int ks = 0; ks < 8; ks++) {
        const int row = warp*16 + lr;
        const int kk = ks*8 + lc;
        qa[ks][0] = __float_as_uint(Kb0[ row   *FS + kk  ]);
        qa[ks][1] = __float_as_uint(Kb0[(row+8)*FS + kk  ]);
        qa[ks][2] = __float_as_uint(Kb0[ row   *FS + kk+4]);
        qa[ks][3] = __float_as_uint(Kb0[(row+8)*FS + kk+4]);
    }
    __syncthreads();

    #pragma unroll
    for (int i = 0; i < 8; i++) {
        const int r = lrow + i*8;
        cp_async16(&Kb0[r*FS + lc4], Kg + r*HDIM + lc4);
        cp_async16(&Vb0[r*FS + lc4], Vg + r*HDIM + lc4);
    }
    CP_COMMIT();
    if (tid < 64)
        msk[tid] = (amask[b*SEQ + tid] == 0) ? -INFINITY : 0.0f;

    float m0 = -INFINITY, m1 = -INFINITY, l0 = 0.0f, l1 = 0.0f;
    float o[8][4];
    #pragma unroll
    for (int nt = 0; nt < 8; nt++)
        #pragma unroll
        for (int q = 0; q < 4; q++) o[nt][q] = 0.0f;

    const int r0g = qt*64 + warp*16 + lr;
    const int r1g = r0g + 8;

    for (int kt = 0; kt <= qt; kt++) {
        const int cur = kt & 1;
        float* Ksc = cur ? Kb1 : Kb0;
        float* Vsc = cur ? Vb1 : Vb0;

        CP_WAIT0();
        __syncthreads();

        if (kt < qt) {
            float* Knx = cur ? Kb0 : Kb1;
            float* Vnx = cur ? Vb0 : Vb1;
            #pragma unroll
            for (int i = 0; i < 8; i++) {
                const int r = lrow + i*8;
                cp_async16(&Knx[r*FS + lc4], Kg + ((kt+1)*64 + r)*HDIM + lc4);
                cp_async16(&Vnx[r*FS + lc4], Vg + ((kt+1)*64 + r)*HDIM + lc4);
            }
            CP_COMMIT();
            if (tid < 64)
                msk[(cur^1)*64 + tid] =
                    (amask[b*SEQ + (kt+1)*64 + tid] == 0) ? -INFINITY : 0.0f;
        }

        float s[8][4];
        #pragma unroll
        for (int nt = 0; nt < 8; nt++)
            #pragma unroll
            for (int q = 0; q < 4; q++) s[nt][q] = 0.0f;

        #pragma unroll
        for (int ks = 0; ks < 8; ks++) {
            #pragma unroll
            for (int nt = 0; nt < 8; nt++) {
                unsigned kb[2];
                kb[0] = __float_as_uint(Ksc[(nt*8 + lr)*FS + ks*8 + lc    ]);
                kb[1] = __float_as_uint(Ksc[(nt*8 + lr)*FS + ks*8 + lc + 4]);
                mma_tf32(s[nt], qa[ks], kb);
            }
        }

        const bool diag = (kt == qt);
        float mx0 = -INFINITY, mx1 = -INFINITY;
        #pragma unroll
        for (int nt = 0; nt < 8; nt++) {
            #pragma unroll
            for (int cc = 0; cc < 2; cc++) {
                const int lcol = nt*8 + 2*lc + cc;
                const float ma = msk[cur*64 + lcol];
                float v0 = s[nt][cc  ]*0.125f + ma;
                float v1 = s[nt][cc+2]*0.125f + ma;
                if (diag) {
                    const int col = kt*64 + lcol;
                    if (col > r0g) v0 = -3.402823466e38f;
                    if (col > r1g) v1 = -3.402823466e38f;
                }
                s[nt][cc  ] = v0;
                s[nt][cc+2] = v1;
                mx0 = fmaxf(mx0, v0);
                mx1 = fmaxf(mx1, v1);
            }
        }
        mx0 = fmaxf(mx0, __shfl_xor_sync(0xffffffffu, mx0, 1));
        mx0 = fmaxf(mx0, __shfl_xor_sync(0xffffffffu, mx0, 2));
        mx1 = fmaxf(mx1, __shfl_xor_sync(0xffffffffu, mx1, 1));
        mx1 = fmaxf(mx1, __shfl_xor_sync(0xffffffffu, mx1, 2));

        const float mn0 = fmaxf(m0, mx0);
        const float mn1 = fmaxf(m1, mx1);
        const float al0 = __expf(m0 - mn0);
        const float al1 = __expf(m1 - mn1);
        float sum0 = 0.0f, sum1 = 0.0f;
        #pragma unroll
        for (int nt = 0; nt < 8; nt++) {
            #pragma unroll
            for (int cc = 0; cc < 2; cc++) {
                const float p0 = tf32r(__expf(s[nt][cc  ] - mn0));
                const float p1 = tf32r(__expf(s[nt][cc+2] - mn1));
                s[nt][cc  ] = p0;
                s[nt][cc+2] = p1;
                sum0 += p0;
                sum1 += p1;
            }
        }
        sum0 += __shfl_xor_sync(0xffffffffu, sum0, 1);
        sum0 += __shfl_xor_sync(0xffffffffu, sum0, 2);
        sum1 += __shfl_xor_sync(0xffffffffu, sum1, 1);
        sum1 += __shfl_xor_sync(0xffffffffu, sum1, 2);
        l0 = l0*al0 + sum0;  m0 = mn0;
        l1 = l1*al1 + sum1;  m1 = mn1;
        #pragma unroll
        for (int nt = 0; nt < 8; nt++) {
            o[nt][0] *= al0; o[nt][1] *= al0;
            o[nt][2] *= al1; o[nt][3] *= al1;
        }

        {
            const int src0 = lr*4 + (lc >> 1);
            const int src1 = src0 + 2;
            const bool odd = lc & 1;
            #pragma unroll
            for (int ks = 0; ks < 8; ks++) {
                const float e0 = __shfl_sync(0xffffffffu, s[ks][0], src0);
                const float e1 = __shfl_sync(0xffffffffu, s[ks][1], src0);
                const float f0 = __shfl_sync(0xffffffffu, s[ks][2], src0);
                const float f1 = __shfl_sync(0xffffffffu, s[ks][3], src0);
                const float g0 = __shfl_sync(0xffffffffu, s[ks][0], src1);
                const float g1 = __shfl_sync(0xffffffffu, s[ks][1], src1);
                const float h0 = __shfl_sync(0xffffffffu, s[ks][2], src1);
                const float h1 = __shfl_sync(0xffffffffu, s[ks][3], src1);
                unsigned pa[4];
                pa[0] = __float_as_uint(odd ? e1 : e0);
                pa[1] = __float_as_uint(odd ? f1 : f0);
                pa[2] = __float_as_uint(odd ? g1 : g0);
                pa[3] = __float_as_uint(odd ? h1 : h0);
                #pragma unroll
                for (int nt = 0; nt < 8; nt++) {
                    unsigned vb[2];
                    vb[0] = __float_as_uint(Vsc[(ks*8 + lc    )*FS + nt*8 + lr]);
                    vb[1] = __float_as_uint(Vsc[(ks*8 + lc + 4)*FS + nt*8 + lr]);
                    mma_tf32(o[nt], pa, vb);
                }
            }
        }
    }

    const float inv0 = 1.0f / l0;
    const float inv1 = 1.0f / l1;
    #pragma unroll
    for (int nt = 0; nt < 8; nt++) {
        const int col = h*HDIM + nt*8 + 2*lc;
        float2 v0, v1;
        v0.x = tf32r(o[nt][0]*inv0); v0.y = tf32r(o[nt][1]*inv0);
        v1.x = tf32r(o[nt][2]*inv1); v1.y = tf32r(o[nt][3]*inv1);
        *(float2*)&g_attn[((size_t)b*SEQ + r0g)*CDIM + col] = v0;
        *(float2*)&g_attn[((size_t)b*SEQ + r1g)*CDIM + col] = v1;
    }
}

// ---------------------------------------------------------------------------
// Kernel 3: proj GEMM [4096,768] @ [768,768] + bias -> out
// (round-12 version: 64x128 tiles, cp.async, cvt only in B-fragment build)
// ---------------------------------------------------------------------------
#define PAS_SZ (64*36)
#define PBS_SZ (32*136)

__global__ __launch_bounds__(256, 3) void proj_gemm_kernel(
    const float* __restrict__ W,      // [768,768] raw fp32
    const float* __restrict__ bias,
    float* __restrict__ out)
{
    extern __shared__ __align__(16) float ds[];
    float* Asb[2] = { ds, ds + PAS_SZ };
    float* Bsb[2] = { ds + 2*PAS_SZ, ds + 2*PAS_SZ + PBS_SZ };

    const int tid = threadIdx.x;
    const int bn = blockIdx.x;
    const int bm = blockIdx.y;
    const int warp = tid >> 5;
    const int lane = tid & 31;
    const int wm = warp >> 2;
    const int wn = warp & 3;
    const int lr = lane >> 2;
    const int lc = lane & 3;

    float acc[2][4][4];
    #pragma unroll
    for (int mi = 0; mi < 2; mi++)
        #pragma unroll
        for (int ni = 0; ni < 4; ni++)
            #pragma unroll
            for (int q = 0; q < 4; q++) acc[mi][ni][q] = 0.0f;

    const int arow = tid >> 3;
    const int ac4  = (tid & 7) << 2;
    const int brow = tid >> 5;
    const int bc4  = (tid & 31) << 2;

    const float* Ag = g_attn + (size_t)(bm*64)*CDIM;   // already tf32-rounded
    const float* Bg = W + bn*128;

    #pragma unroll
    for (int i = 0; i < 2; i++) {
        const int r = arow + i*32;
        cp_async16(&Asb[0][r*36 + ac4], Ag + (size_t)r*CDIM + ac4);
    }
    #pragma unroll
    for (int i = 0; i < 4; i++) {
        const int r = brow + i*8;
        cp_async16(&Bsb[0][r*136 + bc4], Bg + (size_t)r*CDIM + bc4);
    }
    CP_COMMIT();

    for (int it = 0; it < CDIM/32; it++) {
        const int cur = it & 1;
        CP_WAIT0();
        __syncthreads();

        if (it + 1 < CDIM/32) {
            const int k0 = (it+1)*32;
            #pragma unroll
            for (int i = 0; i < 2; i++) {
                const int r = arow + i*32;
                cp_async16(&Asb[cur^1][r*36 + ac4], Ag + (size_t)r*CDIM + k0 + ac4);
            }
            #pragma unroll
            for (int i = 0; i < 4; i++) {
                const int r = brow + i*8;
                cp_async16(&Bsb[cur^1][r*136 + bc4], Bg + (size_t)(k0 + r)*CDIM + bc4);
            }
            CP_COMMIT();
        }

        const float* As = Asb[cur];
        const float* Bs = Bsb[cur];
        #pragma unroll
        for (int ks = 0; ks < 4; ks++) {
            unsigned a[2][4], b[4][2];
            const int kk = ks*8 + lc;
            #pragma unroll
            for (int mi = 0; mi < 2; mi++) {
                const int row = wm*32 + mi*16 + lr;
                a[mi][0] = __float_as_uint(As[ row   *36 + kk  ]);
                a[mi][1] = __float_as_uint(As[(row+8)*36 + kk  ]);
                a[mi][2] = __float_as_uint(As[ row   *36 + kk+4]);
                a[mi][3] = __float_as_uint(As[(row+8)*36 + kk+4]);
            }
            #pragma unroll
            for (int ni = 0; ni < 4; ni++) {
                const int coln = wn*32 + ni*8 + lr;
                b[ni][0] = tf32u(Bs[(ks*8 + lc    )*136 + coln]);
                b[ni][1] = tf32u(Bs[(ks*8 + lc + 4)*136 + coln]);
            }
            #pragma unroll
            for (int mi = 0; mi < 2; mi++)
                #pragma unroll
                for (int ni = 0; ni < 4; ni++)
                    mma_tf32(acc[mi][ni], a[mi], b[ni]);
        }
        __syncthreads();
    }

    #pragma unroll
    for (int mi = 0; mi < 2; mi++) {
        const int r0 = bm*64 + wm*32 + mi*16 + lr;
        const int r1 = r0 + 8;
        #pragma unroll
        for (int ni = 0; ni < 4; ni++) {
            const int n = bn*128 + wn*32 + ni*8 + 2*lc;
            const float b0 = bias[n], b1 = bias[n+1];
            float2 v0, v1;
            v0.x = acc[mi][ni][0] + b0; v0.y = acc[mi][ni][1] + b1;
            v1.x = acc[mi][ni][2] + b0; v1.y = acc[mi][ni][3] + b1;
            *(float2*)&out[(size_t)r0*CDIM + n] = v0;
            *(float2*)&out[(size_t)r1*CDIM + n] = v1;
        }
    }
}

// ---------------------------------------------------------------------------
extern "C" void kernel_launch(void* const* d_in, const int* in_sizes, int n_in,
                              void* d_out, int out_size)
{
    (void)in_sizes; (void)n_in; (void)out_size;
    const float* x      = (const float*)d_in[0];
    const int*   amask  = (const int*)d_in[1];
    const float* W_attn = (const float*)d_in[2];
    const float* b_attn = (const float*)d_in[3];
    const float* W_proj = (const float*)d_in[4];
    const float* b_proj = (const float*)d_in[5];
    float* out = (float*)d_out;

    const int proj_smem = (2*PAS_SZ + 2*PBS_SZ) * (int)sizeof(float); // 53248 B
    cudaFuncSetAttribute(proj_gemm_kernel,
                         cudaFuncAttributeMaxDynamicSharedMemorySize, proj_smem);
    const int flash_smem = (4*KST + 128) * (int)sizeof(float);        // 70144 B
    cudaFuncSetAttribute(flash_kernel,
                         cudaFuncAttributeMaxDynamicSharedMemorySize, flash_smem);

    {
        dim3 grid(N3/128, MROWS/128);    // (18, 32)
        qkv_gemm_kernel<<<grid, 256>>>(x, W_attn, b_attn);
    }
    {
        dim3 grid(BHN, SEQ/64);          // (24, 32): global heavy-first
        flash_kernel<<<grid, 128, flash_smem>>>(amask);
    }
    {
        dim3 grid(CDIM/128, MROWS/64);   // (6, 64) = 384 blocks
        proj_gemm_kernel<<<grid, 256, proj_smem>>>(W_proj, b_proj, out);
    }
}

// round 16
// speedup vs baseline: 1.2005x; 1.0028x over previous
#include <cuda_runtime.h>
#include <math.h>
#include <float.h>

// Problem constants
#define BATCH 2
#define SEQ   2048
#define CDIM  768
#define NHEAD 12
#define HDIM  64
#define MROWS (BATCH*SEQ)     // 4096
#define N3    (3*CDIM)        // 2304
#define BHN   (BATCH*NHEAD)   // 24

// Scratch (device globals; no allocation allowed)
__device__ float g_Q[BATCH*NHEAD*SEQ*HDIM];
__device__ float g_K[BATCH*NHEAD*SEQ*HDIM];
__device__ float g_V[BATCH*NHEAD*SEQ*HDIM];
__device__ float g_attn[BATCH*SEQ*CDIM];

// ---------------------------------------------------------------------------
// helpers
// ---------------------------------------------------------------------------
__device__ __forceinline__ float tf32r(float x) {
    unsigned u;
    asm("cvt.rna.tf32.f32 %0, %1;" : "=r"(u) : "f"(x));
    return __uint_as_float(u);
}
__device__ __forceinline__ unsigned tf32u(float x) {
    unsigned u;
    asm("cvt.rna.tf32.f32 %0, %1;" : "=r"(u) : "f"(x));
    return u;
}

__device__ __forceinline__ void mma_tf32(float* c, const unsigned* a, const unsigned* b) {
    asm volatile(
        "mma.sync.aligned.m16n8k8.row.col.f32.tf32.tf32.f32 "
        "{%0,%1,%2,%3},{%4,%5,%6,%7},{%8,%9},{%0,%1,%2,%3};\n"
        : "+f"(c[0]), "+f"(c[1]), "+f"(c[2]), "+f"(c[3])
        : "r"(a[0]), "r"(a[1]), "r"(a[2]), "r"(a[3]), "r"(b[0]), "r"(b[1]));
}

__device__ __forceinline__ void cp_async16(float* smem_dst, const float* gmem_src) {
    unsigned saddr = (unsigned)__cvta_generic_to_shared(smem_dst);
    asm volatile("cp.async.cg.shared.global [%0], [%1], 16;\n"
                 :: "r"(saddr), "l"(gmem_src));
}
#define CP_COMMIT() asm volatile("cp.async.commit_group;\n" ::: "memory")
#define CP_WAIT0()  asm volatile("cp.async.wait_group 0;\n" ::: "memory")

// ---------------------------------------------------------------------------
// Kernel 1: QKV GEMM  [4096,768] @ [768,2304] + bias, scatter into Q/K/V
// Round-4 version: static smem, LDG->cvt->STS (cvt off the MMA-issue path)
// ---------------------------------------------------------------------------
__global__ __launch_bounds__(256, 2) void qkv_gemm_kernel(
    const float* __restrict__ A,      // x [4096,768]
    const float* __restrict__ W,      // [768,2304]
    const float* __restrict__ bias)   // [2304]
{
    __shared__ __align__(16) float As[128][36];
    __shared__ __align__(16) float Bs[32][136];

    const int tid = threadIdx.x;
    const int bn = blockIdx.x;   // 0..17
    const int bm = blockIdx.y;   // 0..31
    const int warp = tid >> 5;
    const int lane = tid & 31;
    const int wm = warp >> 2;
    const int wn = warp & 3;
    const int lr = lane >> 2;
    const int lc = lane & 3;

    float acc[4][4][4];
    #pragma unroll
    for (int mi = 0; mi < 4; mi++)
        #pragma unroll
        for (int ni = 0; ni < 4; ni++)
            #pragma unroll
            for (int q = 0; q < 4; q++) acc[mi][ni][q] = 0.0f;

    const int arow = tid >> 3;
    const int ac4  = (tid & 7) << 2;
    const int brow = tid >> 5;
    const int bc4  = (tid & 31) << 2;

    for (int k0 = 0; k0 < CDIM; k0 += 32) {
        #pragma unroll
        for (int i = 0; i < 4; i++) {
            const int r = arow + i*32;
            float4 v = *(const float4*)(A + (size_t)(bm*128 + r)*CDIM + k0 + ac4);
            float4 t;
            t.x = tf32r(v.x); t.y = tf32r(v.y); t.z = tf32r(v.z); t.w = tf32r(v.w);
            *(float4*)&As[r][ac4] = t;
        }
        #pragma unroll
        for (int i = 0; i < 4; i++) {
            const int r = brow + i*8;
            float4 v = *(const float4*)(W + (size_t)(k0 + r)*N3 + bn*128 + bc4);
            float4 t;
            t.x = tf32r(v.x); t.y = tf32r(v.y); t.z = tf32r(v.z); t.w = tf32r(v.w);
            *(float4*)&Bs[r][bc4] = t;
        }
        __syncthreads();

        #pragma unroll
        for (int ks = 0; ks < 4; ks++) {
            unsigned a[4][4], b[4][2];
            const int kk = ks*8 + lc;
            #pragma unroll
            for (int mi = 0; mi < 4; mi++) {
                const int row = wm*64 + mi*16 + lr;
                a[mi][0] = __float_as_uint(As[row  ][kk  ]);
                a[mi][1] = __float_as_uint(As[row+8][kk  ]);
                a[mi][2] = __float_as_uint(As[row  ][kk+4]);
                a[mi][3] = __float_as_uint(As[row+8][kk+4]);
            }
            #pragma unroll
            for (int ni = 0; ni < 4; ni++) {
                const int coln = wn*32 + ni*8 + lr;
                b[ni][0] = __float_as_uint(Bs[ks*8 + lc    ][coln]);
                b[ni][1] = __float_as_uint(Bs[ks*8 + lc + 4][coln]);
            }
            #pragma unroll
            for (int mi = 0; mi < 4; mi++)
                #pragma unroll
                for (int ni = 0; ni < 4; ni++)
                    mma_tf32(acc[mi][ni], a[mi], b[ni]);
        }
        __syncthreads();
    }

    #pragma unroll
    for (int mi = 0; mi < 4; mi++) {
        const int r0 = bm*128 + wm*64 + mi*16 + lr;
        const int r1 = r0 + 8;
        #pragma unroll
        for (int ni = 0; ni < 4; ni++) {
            const int n = bn*128 + wn*32 + ni*8 + 2*lc;
            const float b0 = bias[n], b1 = bias[n+1];
            const int part = n / CDIM;
            const int rr = n % CDIM;
            const int h = rr >> 6;
            const int d = rr & 63;
            float* dst = (part == 0) ? g_Q : (part == 1) ? g_K : g_V;
            {
                const int bb = r0 >> 11, t = r0 & 2047;
                float2 v;
                v.x = tf32r(acc[mi][ni][0] + b0);
                v.y = tf32r(acc[mi][ni][1] + b1);
                *(float2*)&dst[(((size_t)bb*NHEAD + h)*SEQ + t)*HDIM + d] = v;
            }
            {
                const int bb = r1 >> 11, t = r1 & 2047;
                float2 v;
                v.x = tf32r(acc[mi][ni][2] + b0);
                v.y = tf32r(acc[mi][ni][3] + b1);
                *(float2*)&dst[(((size_t)bb*NHEAD + h)*SEQ + t)*HDIM + d] = v;
            }
        }
    }
}

// ---------------------------------------------------------------------------
// Kernel 2: flash attention (round-15 body + exp2-domain softmax)
// ---------------------------------------------------------------------------
#define FS 68
#define KST (64*FS)
#define SCL2 0.18033688011112042f   // 0.125 * log2(e)

__global__ __launch_bounds__(128, 3) void flash_kernel(const int* __restrict__ amask)
{
    extern __shared__ __align__(16) float dsm[];
    float* Kb0 = dsm;
    float* Kb1 = dsm + KST;
    float* Vb0 = dsm + 2*KST;
    float* Vb1 = dsm + 3*KST;
    float* msk = dsm + 4*KST;

    const int bh = blockIdx.x;       // 0..23  (fastest axis)
    const int qt = 31 - blockIdx.y;  // heavy-first globally
    const int b  = bh / NHEAD;
    const int h  = bh % NHEAD;

    const float* Qg = g_Q + (size_t)bh*SEQ*HDIM + qt*64*HDIM;
    const float* Kg = g_K + (size_t)bh*SEQ*HDIM;
    const float* Vg = g_V + (size_t)bh*SEQ*HDIM;

    const int tid = threadIdx.x;
    const int warp = tid >> 5;
    const int lane = tid & 31;
    const int lr = lane >> 2;
    const int lc = lane & 3;

    const int lrow = tid >> 4;
    const int lc4  = (tid & 15) << 2;

    #pragma unroll
    for (int i = 0; i < 8; i++) {
        const int r = lrow + i*8;
        *(float4*)&Kb0[r*FS + lc4] = *(const float4*)(Qg + r*HDIM + lc4);
    }
    __syncthreads();

    unsigned qa[8][4];
    #pragma unroll
    for (int ks = 0; ks < 8; ks++) {
        const int row = warp*16 + lr;
        const int kk = ks*8 + lc;
        qa[ks][0] = __float_as_uint(Kb0[ row   *FS + kk  ]);
        qa[ks][1] = __float_as_uint(Kb0[(row+8)*FS + kk  ]);
        qa[ks][2] = __float_as_uint(Kb0[ row   *FS + kk+4]);
        qa[ks][3] = __float_as_uint(Kb0[(row+8)*FS + kk+4]);
    }
    __syncthreads();

    #pragma unroll
    for (int i = 0; i < 8; i++) {
        const int r = lrow + i*8;
        cp_async16(&Kb0[r*FS + lc4], Kg + r*HDIM + lc4);
        cp_async16(&Vb0[r*FS + lc4], Vg + r*HDIM + lc4);
    }
    CP_COMMIT();
    if (tid < 64)
        msk[tid] = (amask[b*SEQ + tid] == 0) ? -INFINITY : 0.0f;

    float m0 = -INFINITY, m1 = -INFINITY, l0 = 0.0f, l1 = 0.0f;
    float o[8][4];
    #pragma unroll
    for (int nt = 0; nt < 8; nt++)
        #pragma unroll
        for (int q = 0; q < 4; q++) o[nt][q] = 0.0f;

    const int r0g = qt*64 + warp*16 + lr;
    const int r1g = r0g + 8;

    for (int kt = 0; kt <= qt; kt++) {
        const int cur = kt & 1;
        float* Ksc = cur ? Kb1 : Kb0;
        float* Vsc = cur ? Vb1 : Vb0;

        CP_WAIT0();
        __syncthreads();

        if (kt < qt) {
            float* Knx = cur ? Kb0 : Kb1;
            float* Vnx = cur ? Vb0 : Vb1;
            #pragma unroll
            for (int i = 0; i < 8; i++) {
                const int r = lrow + i*8;
                cp_async16(&Knx[r*FS + lc4], Kg + ((kt+1)*64 + r)*HDIM + lc4);
                cp_async16(&Vnx[r*FS + lc4], Vg + ((kt+1)*64 + r)*HDIM + lc4);
            }
            CP_COMMIT();
            if (tid < 64)
                msk[(cur^1)*64 + tid] =
                    (amask[b*SEQ + (kt+1)*64 + tid] == 0) ? -INFINITY : 0.0f;
        }

        float s[8][4];
        #pragma unroll
        for (int nt = 0; nt < 8; nt++)
            #pragma unroll
            for (int q = 0; q < 4; q++) s[nt][q] = 0.0f;

        #pragma unroll
        for (int ks = 0; ks < 8; ks++) {
            #pragma unroll
            for (int nt = 0; nt < 8; nt++) {
                unsigned kb[2];
                kb[0] = __float_as_uint(Ksc[(nt*8 + lr)*FS + ks*8 + lc    ]);
                kb[1] = __float_as_uint(Ksc[(nt*8 + lr)*FS + ks*8 + lc + 4]);
                mma_tf32(s[nt], qa[ks], kb);
            }
        }

        // exp2-domain softmax: logits scaled by 0.125*log2(e); exp(x) == 2^(x*log2e)
        const bool diag = (kt == qt);
        float mx0 = -INFINITY, mx1 = -INFINITY;
        #pragma unroll
        for (int nt = 0; nt < 8; nt++) {
            #pragma unroll
            for (int cc = 0; cc < 2; cc++) {
                const int lcol = nt*8 + 2*lc + cc;
                const float ma = msk[cur*64 + lcol];
                float v0 = fmaf(s[nt][cc  ], SCL2, ma);
                float v1 = fmaf(s[nt][cc+2], SCL2, ma);
                if (diag) {
                    const int col = kt*64 + lcol;
                    if (col > r0g) v0 = -3.402823466e38f;
                    if (col > r1g) v1 = -3.402823466e38f;
                }
                s[nt][cc  ] = v0;
                s[nt][cc+2] = v1;
                mx0 = fmaxf(mx0, v0);
                mx1 = fmaxf(mx1, v1);
            }
        }
        mx0 = fmaxf(mx0, __shfl_xor_sync(0xffffffffu, mx0, 1));
        mx0 = fmaxf(mx0, __shfl_xor_sync(0xffffffffu, mx0, 2));
        mx1 = fmaxf(mx1, __shfl_xor_sync(0xffffffffu, mx1, 1));
        mx1 = fmaxf(mx1, __shfl_xor_sync(0xffffffffu, mx1, 2));

        const float mn0 = fmaxf(m0, mx0);
        const float mn1 = fmaxf(m1, mx1);
        const float al0 = exp2f(m0 - mn0);
        const float al1 = exp2f(m1 - mn1);
        float sum0 = 0.0f, sum1 = 0.0f;
        #pragma unroll
        for (int nt = 0; nt < 8; nt++) {
            #pragma unroll
            for (int cc = 0; cc < 2; cc++) {
                const float p0 = tf32r(exp2f(s[nt][cc  ] - mn0));
                const float p1 = tf32r(exp2f(s[nt][cc+2] - mn1));
                s[nt][cc  ] = p0;
                s[nt][cc+2] = p1;
                sum0 += p0;
                sum1 += p1;
            }
        }
        sum0 += __shfl_xor_sync(0xffffffffu, sum0, 1);
        sum0 += __shfl_xor_sync(0xffffffffu, sum0, 2);
        sum1 += __shfl_xor_sync(0xffffffffu, sum1, 1);
        sum1 += __shfl_xor_sync(0xffffffffu, sum1, 2);
        l0 = l0*al0 + sum0;  m0 = mn0;
        l1 = l1*al1 + sum1;  m1 = mn1;
        #pragma unroll
        for (int nt = 0; nt < 8; nt++) {
            o[nt][0] *= al0; o[nt][1] *= al0;
            o[nt][2] *= al1; o[nt][3] *= al1;
        }

        {
            const int src0 = lr*4 + (lc >> 1);
            const int src1 = src0 + 2;
            const bool odd = lc & 1;
            #pragma unroll
            for (int ks = 0; ks < 8; ks++) {
                const float e0 = __shfl_sync(0xffffffffu, s[ks][0], src0);
                const float e1 = __shfl_sync(0xffffffffu, s[ks][1], src0);
                const float f0 = __shfl_sync(0xffffffffu, s[ks][2], src0);
                const float f1 = __shfl_sync(0xffffffffu, s[ks][3], src0);
                const float g0 = __shfl_sync(0xffffffffu, s[ks][0], src1);
                const float g1 = __shfl_sync(0xffffffffu, s[ks][1], src1);
                const float h0 = __shfl_sync(0xffffffffu, s[ks][2], src1);
                const float h1 = __shfl_sync(0xffffffffu, s[ks][3], src1);
                unsigned pa[4];
                pa[0] = __float_as_uint(odd ? e1 : e0);
                pa[1] = __float_as_uint(odd ? f1 : f0);
                pa[2] = __float_as_uint(odd ? g1 : g0);
                pa[3] = __float_as_uint(odd ? h1 : h0);
                #pragma unroll
                for (int nt = 0; nt < 8; nt++) {
                    unsigned vb[2];
                    vb[0] = __float_as_uint(Vsc[(ks*8 + lc    )*FS + nt*8 + lr]);
                    vb[1] = __float_as_uint(Vsc[(ks*8 + lc + 4)*FS + nt*8 + lr]);
                    mma_tf32(o[nt], pa, vb);
                }
            }
        }
    }

    const float inv0 = 1.0f / l0;
    const float inv1 = 1.0f / l1;
    #pragma unroll
    for (int nt = 0; nt < 8; nt++) {
        const int col = h*HDIM + nt*8 + 2*lc;
        float2 v0, v1;
        v0.x = tf32r(o[nt][0]*inv0); v0.y = tf32r(o[nt][1]*inv0);
        v1.x = tf32r(o[nt][2]*inv1); v1.y = tf32r(o[nt][3]*inv1);
        *(float2*)&g_attn[((size_t)b*SEQ + r0g)*CDIM + col] = v0;
        *(float2*)&g_attn[((size_t)b*SEQ + r1g)*CDIM + col] = v1;
    }
}

// ---------------------------------------------------------------------------
// Kernel 3: proj GEMM [4096,768] @ [768,768] + bias -> out (unchanged)
// ---------------------------------------------------------------------------
#define PAS_SZ (64*36)
#define PBS_SZ (32*136)

__global__ __launch_bounds__(256, 3) void proj_gemm_kernel(
    const float* __restrict__ W,      // [768,768] raw fp32
    const float* __restrict__ bias,
    float* __restrict__ out)
{
    extern __shared__ __align__(16) float ds[];
    float* Asb[2] = { ds, ds + PAS_SZ };
    float* Bsb[2] = { ds + 2*PAS_SZ, ds + 2*PAS_SZ + PBS_SZ };

    const int tid = threadIdx.x;
    const int bn = blockIdx.x;
    const int bm = blockIdx.y;
    const int warp = tid >> 5;
    const int lane = tid & 31;
    const int wm = warp >> 2;
    const int wn = warp & 3;
    const int lr = lane >> 2;
    const int lc = lane & 3;

    float acc[2][4][4];
    #pragma unroll
    for (int mi = 0; mi < 2; mi++)
        #pragma unroll
        for (int ni = 0; ni < 4; ni++)
            #pragma unroll
            for (int q = 0; q < 4; q++) acc[mi][ni][q] = 0.0f;

    const int arow = tid >> 3;
    const int ac4  = (tid & 7) << 2;
    const int brow = tid >> 5;
    const int bc4  = (tid & 31) << 2;

    const float* Ag = g_attn + (size_t)(bm*64)*CDIM;   // already tf32-rounded
    const float* Bg = W + bn*128;

    #pragma unroll
    for (int i = 0; i < 2; i++) {
        const int r = arow + i*32;
        cp_async16(&Asb[0][r*36 + ac4], Ag + (size_t)r*CDIM + ac4);
    }
    #pragma unroll
    for (int i = 0; i < 4; i++) {
        const int r = brow + i*8;
        cp_async16(&Bsb[0][r*136 + bc4], Bg + (size_t)r*CDIM + bc4);
    }
    CP_COMMIT();

    for (int it = 0; it < CDIM/32; it++) {
        const int cur = it & 1;
        CP_WAIT0();
        __syncthreads();

        if (it + 1 < CDIM/32) {
            const int k0 = (it+1)*32;
            #pragma unroll
            for (int i = 0; i < 2; i++) {
                const int r = arow + i*32;
                cp_async16(&Asb[cur^1][r*36 + ac4], Ag + (size_t)r*CDIM + k0 + ac4);
            }
            #pragma unroll
            for (int i = 0; i < 4; i++) {
                const int r = brow + i*8;
                cp_async16(&Bsb[cur^1][r*136 + bc4], Bg + (size_t)(k0 + r)*CDIM + bc4);
            }
            CP_COMMIT();
        }

        const float* As = Asb[cur];
        const float* Bs = Bsb[cur];
        #pragma unroll
        for (int ks = 0; ks < 4; ks++) {
            unsigned a[2][4], b[4][2];
            const int kk = ks*8 + lc;
            #pragma unroll
            for (int mi = 0; mi < 2; mi++) {
                const int row = wm*32 + mi*16 + lr;
                a[mi][0] = __float_as_uint(As[ row   *36 + kk  ]);
                a[mi][1] = __float_as_uint(As[(row+8)*36 + kk  ]);
                a[mi][2] = __float_as_uint(As[ row   *36 + kk+4]);
                a[mi][3] = __float_as_uint(As[(row+8)*36 + kk+4]);
            }
            #pragma unroll
            for (int ni = 0; ni < 4; ni++) {
                const int coln = wn*32 + ni*8 + lr;
                b[ni][0] = tf32u(Bs[(ks*8 + lc    )*136 + coln]);
                b[ni][1] = tf32u(Bs[(ks*8 + lc + 4)*136 + coln]);
            }
            #pragma unroll
            for (int mi = 0; mi < 2; mi++)
                #pragma unroll
                for (int ni = 0; ni < 4; ni++)
                    mma_tf32(acc[mi][ni], a[mi], b[ni]);
        }
        __syncthreads();
    }

    #pragma unroll
    for (int mi = 0; mi < 2; mi++) {
        const int r0 = bm*64 + wm*32 + mi*16 + lr;
        const int r1 = r0 + 8;
        #pragma unroll
        for (int ni = 0; ni < 4; ni++) {
            const int n = bn*128 + wn*32 + ni*8 + 2*lc;
            const float b0 = bias[n], b1 = bias[n+1];
            float2 v0, v1;
            v0.x = acc[mi][ni][0] + b0; v0.y = acc[mi][ni][1] + b1;
            v1.x = acc[mi][ni][2] + b0; v1.y = acc[mi][ni][3] + b1;
            *(float2*)&out[(size_t)r0*CDIM + n] = v0;
            *(float2*)&out[(size_t)r1*CDIM + n] = v1;
        }
    }
}

// ---------------------------------------------------------------------------
extern "C" void kernel_launch(void* const* d_in, const int* in_sizes, int n_in,
                              void* d_out, int out_size)
{
    (void)in_sizes; (void)n_in; (void)out_size;
    const float* x      = (const float*)d_in[0];
    const int*   amask  = (const int*)d_in[1];
    const float* W_attn = (const float*)d_in[2];
    const float* b_attn = (const float*)d_in[3];
    const float* W_proj = (const float*)d_in[4];
    const float* b_proj = (const float*)d_in[5];
    float* out = (float*)d_out;

    const int proj_smem = (2*PAS_SZ + 2*PBS_SZ) * (int)sizeof(float); // 53248 B
    cudaFuncSetAttribute(proj_gemm_kernel,
                         cudaFuncAttributeMaxDynamicSharedMemorySize, proj_smem);
    const int flash_smem = (4*KST + 128) * (int)sizeof(float);        // 70144 B
    cudaFuncSetAttribute(flash_kernel,
                         cudaFuncAttributeMaxDynamicSharedMemorySize, flash_smem);

    {
        dim3 grid(N3/128, MROWS/128);    // (18, 32)
        qkv_gemm_kernel<<<grid, 256>>>(x, W_attn, b_attn);
    }
    {
        dim3 grid(BHN, SEQ/64);          // (24, 32): global heavy-first
        flash_kernel<<<grid, 128, flash_smem>>>(amask);
    }
    {
        dim3 grid(CDIM/128, MROWS/64);   // (6, 64) = 384 blocks
        proj_gemm_kernel<<<grid, 256, proj_smem>>>(W_proj, b_proj, out);
    }
}

// round 17
// speedup vs baseline: 1.2096x; 1.0076x over previous
#include <cuda_runtime.h>
#include <math.h>
#include <float.h>

// Problem constants
#define BATCH 2
#define SEQ   2048
#define CDIM  768
#define NHEAD 12
#define HDIM  64
#define MROWS (BATCH*SEQ)     // 4096
#define N3    (3*CDIM)        // 2304
#define BHN   (BATCH*NHEAD)   // 24

// Scratch (device globals; no allocation allowed)
__device__ float g_Q[BATCH*NHEAD*SEQ*HDIM];
__device__ float g_K[BATCH*NHEAD*SEQ*HDIM];
__device__ float g_V[BATCH*NHEAD*SEQ*HDIM];
__device__ float g_attn[BATCH*SEQ*CDIM];

// ---------------------------------------------------------------------------
// helpers
// ---------------------------------------------------------------------------
__device__ __forceinline__ float tf32r(float x) {
    unsigned u;
    asm("cvt.rna.tf32.f32 %0, %1;" : "=r"(u) : "f"(x));
    return __uint_as_float(u);
}
__device__ __forceinline__ unsigned tf32u(float x) {
    unsigned u;
    asm("cvt.rna.tf32.f32 %0, %1;" : "=r"(u) : "f"(x));
    return u;
}

__device__ __forceinline__ void mma_tf32(float* c, const unsigned* a, const unsigned* b) {
    asm volatile(
        "mma.sync.aligned.m16n8k8.row.col.f32.tf32.tf32.f32 "
        "{%0,%1,%2,%3},{%4,%5,%6,%7},{%8,%9},{%0,%1,%2,%3};\n"
        : "+f"(c[0]), "+f"(c[1]), "+f"(c[2]), "+f"(c[3])
        : "r"(a[0]), "r"(a[1]), "r"(a[2]), "r"(a[3]), "r"(b[0]), "r"(b[1]));
}

__device__ __forceinline__ void cp_async16(float* smem_dst, const float* gmem_src) {
    unsigned saddr = (unsigned)__cvta_generic_to_shared(smem_dst);
    asm volatile("cp.async.cg.shared.global [%0], [%1], 16;\n"
                 :: "r"(saddr), "l"(gmem_src));
}
#define CP_COMMIT() asm volatile("cp.async.commit_group;\n" ::: "memory")
#define CP_WAIT0()  asm volatile("cp.async.wait_group 0;\n" ::: "memory")

// ---------------------------------------------------------------------------
// Kernel 1: QKV GEMM  [4096,768] @ [768,2304] + bias, scatter into Q/K/V
// Round-4 version: static smem, LDG->cvt->STS (cvt off the MMA-issue path)
// ---------------------------------------------------------------------------
__global__ __launch_bounds__(256, 2) void qkv_gemm_kernel(
    const float* __restrict__ A,      // x [4096,768]
    const float* __restrict__ W,      // [768,2304]
    const float* __restrict__ bias)   // [2304]
{
    __shared__ __align__(16) float As[128][36];
    __shared__ __align__(16) float Bs[32][136];

    const int tid = threadIdx.x;
    const int bn = blockIdx.x;   // 0..17
    const int bm = blockIdx.y;   // 0..31
    const int warp = tid >> 5;
    const int lane = tid & 31;
    const int wm = warp >> 2;
    const int wn = warp & 3;
    const int lr = lane >> 2;
    const int lc = lane & 3;

    float acc[4][4][4];
    #pragma unroll
    for (int mi = 0; mi < 4; mi++)
        #pragma unroll
        for (int ni = 0; ni < 4; ni++)
            #pragma unroll
            for (int q = 0; q < 4; q++) acc[mi][ni][q] = 0.0f;

    const int arow = tid >> 3;
    const int ac4  = (tid & 7) << 2;
    const int brow = tid >> 5;
    const int bc4  = (tid & 31) << 2;

    for (int k0 = 0; k0 < CDIM; k0 += 32) {
        #pragma unroll
        for (int i = 0; i < 4; i++) {
            const int r = arow + i*32;
            float4 v = *(const float4*)(A + (size_t)(bm*128 + r)*CDIM + k0 + ac4);
            float4 t;
            t.x = tf32r(v.x); t.y = tf32r(v.y); t.z = tf32r(v.z); t.w = tf32r(v.w);
            *(float4*)&As[r][ac4] = t;
        }
        #pragma unroll
        for (int i = 0; i < 4; i++) {
            const int r = brow + i*8;
            float4 v = *(const float4*)(W + (size_t)(k0 + r)*N3 + bn*128 + bc4);
            float4 t;
            t.x = tf32r(v.x); t.y = tf32r(v.y); t.z = tf32r(v.z); t.w = tf32r(v.w);
            *(float4*)&Bs[r][bc4] = t;
        }
        __syncthreads();

        #pragma unroll
        for (int ks = 0; ks < 4; ks++) {
            unsigned a[4][4], b[4][2];
            const int kk = ks*8 + lc;
            #pragma unroll
            for (int mi = 0; mi < 4; mi++) {
                const int row = wm*64 + mi*16 + lr;
                a[mi][0] = __float_as_uint(As[row  ][kk  ]);
                a[mi][1] = __float_as_uint(As[row+8][kk  ]);
                a[mi][2] = __float_as_uint(As[row  ][kk+4]);
                a[mi][3] = __float_as_uint(As[row+8][kk+4]);
            }
            #pragma unroll
            for (int ni = 0; ni < 4; ni++) {
                const int coln = wn*32 + ni*8 + lr;
                b[ni][0] = __float_as_uint(Bs[ks*8 + lc    ][coln]);
                b[ni][1] = __float_as_uint(Bs[ks*8 + lc + 4][coln]);
            }
            #pragma unroll
            for (int mi = 0; mi < 4; mi++)
                #pragma unroll
                for (int ni = 0; ni < 4; ni++)
                    mma_tf32(acc[mi][ni], a[mi], b[ni]);
        }
        __syncthreads();
    }

    #pragma unroll
    for (int mi = 0; mi < 4; mi++) {
        const int r0 = bm*128 + wm*64 + mi*16 + lr;
        const int r1 = r0 + 8;
        #pragma unroll
        for (int ni = 0; ni < 4; ni++) {
            const int n = bn*128 + wn*32 + ni*8 + 2*lc;
            const float b0 = bias[n], b1 = bias[n+1];
            const int part = n / CDIM;
            const int rr = n % CDIM;
            const int h = rr >> 6;
            const int d = rr & 63;
            float* dst = (part == 0) ? g_Q : (part == 1) ? g_K : g_V;
            {
                const int bb = r0 >> 11, t = r0 & 2047;
                float2 v;
                v.x = tf32r(acc[mi][ni][0] + b0);
                v.y = tf32r(acc[mi][ni][1] + b1);
                *(float2*)&dst[(((size_t)bb*NHEAD + h)*SEQ + t)*HDIM + d] = v;
            }
            {
                const int bb = r1 >> 11, t = r1 & 2047;
                float2 v;
                v.x = tf32r(acc[mi][ni][2] + b0);
                v.y = tf32r(acc[mi][ni][3] + b1);
                *(float2*)&dst[(((size_t)bb*NHEAD + h)*SEQ + t)*HDIM + d] = v;
            }
        }
    }
}

// ---------------------------------------------------------------------------
// Kernel 2: flash attention (round-16 body; P fed to MMA without explicit
// tf32 cvt — HW reads tf32 bits, softmax outputs are well-conditioned)
// ---------------------------------------------------------------------------
#define FS 68
#define KST (64*FS)
#define SCL2 0.18033688011112042f   // 0.125 * log2(e)

__global__ __launch_bounds__(128, 3) void flash_kernel(const int* __restrict__ amask)
{
    extern __shared__ __align__(16) float dsm[];
    float* Kb0 = dsm;
    float* Kb1 = dsm + KST;
    float* Vb0 = dsm + 2*KST;
    float* Vb1 = dsm + 3*KST;
    float* msk = dsm + 4*KST;

    const int bh = blockIdx.x;       // 0..23  (fastest axis)
    const int qt = 31 - blockIdx.y;  // heavy-first globally
    const int b  = bh / NHEAD;
    const int h  = bh % NHEAD;

    const float* Qg = g_Q + (size_t)bh*SEQ*HDIM + qt*64*HDIM;
    const float* Kg = g_K + (size_t)bh*SEQ*HDIM;
    const float* Vg = g_V + (size_t)bh*SEQ*HDIM;

    const int tid = threadIdx.x;
    const int warp = tid >> 5;
    const int lane = tid & 31;
    const int lr = lane >> 2;
    const int lc = lane & 3;

    const int lrow = tid >> 4;
    const int lc4  = (tid & 15) << 2;

    #pragma unroll
    for (int i = 0; i < 8; i++) {
        const int r = lrow + i*8;
        *(float4*)&Kb0[r*FS + lc4] = *(const float4*)(Qg + r*HDIM + lc4);
    }
    __syncthreads();

    unsigned qa[8][4];
    #pragma unroll
    for (int ks = 0; ks < 8; ks++) {
        const int row = warp*16 + lr;
        const int kk = ks*8 + lc;
        qa[ks][0] = __float_as_uint(Kb0[ row   *FS + kk  ]);
        qa[ks][1] = __float_as_uint(Kb0[(row+8)*FS + kk  ]);
        qa[ks][2] = __float_as_uint(Kb0[ row   *FS + kk+4]);
        qa[ks][3] = __float_as_uint(Kb0[(row+8)*FS + kk+4]);
    }
    __syncthreads();

    #pragma unroll
    for (int i = 0; i < 8; i++) {
        const int r = lrow + i*8;
        cp_async16(&Kb0[r*FS + lc4], Kg + r*HDIM + lc4);
        cp_async16(&Vb0[r*FS + lc4], Vg + r*HDIM + lc4);
    }
    CP_COMMIT();
    if (tid < 64)
        msk[tid] = (amask[b*SEQ + tid] == 0) ? -INFINITY : 0.0f;

    float m0 = -INFINITY, m1 = -INFINITY, l0 = 0.0f, l1 = 0.0f;
    float o[8][4];
    #pragma unroll
    for (int nt = 0; nt < 8; nt++)
        #pragma unroll
        for (int q = 0; q < 4; q++) o[nt][q] = 0.0f;

    const int r0g = qt*64 + warp*16 + lr;
    const int r1g = r0g + 8;

    for (int kt = 0; kt <= qt; kt++) {
        const int cur = kt & 1;
        float* Ksc = cur ? Kb1 : Kb0;
        float* Vsc = cur ? Vb1 : Vb0;

        CP_WAIT0();
        __syncthreads();

        if (kt < qt) {
            float* Knx = cur ? Kb0 : Kb1;
            float* Vnx = cur ? Vb0 : Vb1;
            #pragma unroll
            for (int i = 0; i < 8; i++) {
                const int r = lrow + i*8;
                cp_async16(&Knx[r*FS + lc4], Kg + ((kt+1)*64 + r)*HDIM + lc4);
                cp_async16(&Vnx[r*FS + lc4], Vg + ((kt+1)*64 + r)*HDIM + lc4);
            }
            CP_COMMIT();
            if (tid < 64)
                msk[(cur^1)*64 + tid] =
                    (amask[b*SEQ + (kt+1)*64 + tid] == 0) ? -INFINITY : 0.0f;
        }

        float s[8][4];
        #pragma unroll
        for (int nt = 0; nt < 8; nt++)
            #pragma unroll
            for (int q = 0; q < 4; q++) s[nt][q] = 0.0f;

        #pragma unroll
        for (int ks = 0; ks < 8; ks++) {
            #pragma unroll
            for (int nt = 0; nt < 8; nt++) {
                unsigned kb[2];
                kb[0] = __float_as_uint(Ksc[(nt*8 + lr)*FS + ks*8 + lc    ]);
                kb[1] = __float_as_uint(Ksc[(nt*8 + lr)*FS + ks*8 + lc + 4]);
                mma_tf32(s[nt], qa[ks], kb);
            }
        }

        // exp2-domain softmax: logits scaled by 0.125*log2(e)
        const bool diag = (kt == qt);
        float mx0 = -INFINITY, mx1 = -INFINITY;
        #pragma unroll
        for (int nt = 0; nt < 8; nt++) {
            #pragma unroll
            for (int cc = 0; cc < 2; cc++) {
                const int lcol = nt*8 + 2*lc + cc;
                const float ma = msk[cur*64 + lcol];
                float v0 = fmaf(s[nt][cc  ], SCL2, ma);
                float v1 = fmaf(s[nt][cc+2], SCL2, ma);
                if (diag) {
                    const int col = kt*64 + lcol;
                    if (col > r0g) v0 = -3.402823466e38f;
                    if (col > r1g) v1 = -3.402823466e38f;
                }
                s[nt][cc  ] = v0;
                s[nt][cc+2] = v1;
                mx0 = fmaxf(mx0, v0);
                mx1 = fmaxf(mx1, v1);
            }
        }
        mx0 = fmaxf(mx0, __shfl_xor_sync(0xffffffffu, mx0, 1));
        mx0 = fmaxf(mx0, __shfl_xor_sync(0xffffffffu, mx0, 2));
        mx1 = fmaxf(mx1, __shfl_xor_sync(0xffffffffu, mx1, 1));
        mx1 = fmaxf(mx1, __shfl_xor_sync(0xffffffffu, mx1, 2));

        const float mn0 = fmaxf(m0, mx0);
        const float mn1 = fmaxf(m1, mx1);
        const float al0 = exp2f(m0 - mn0);
        const float al1 = exp2f(m1 - mn1);
        float sum0 = 0.0f, sum1 = 0.0f;
        #pragma unroll
        for (int nt = 0; nt < 8; nt++) {
            #pragma unroll
            for (int cc = 0; cc < 2; cc++) {
                const float p0 = exp2f(s[nt][cc  ] - mn0);
                const float p1 = exp2f(s[nt][cc+2] - mn1);
                s[nt][cc  ] = p0;
                s[nt][cc+2] = p1;
                sum0 += p0;
                sum1 += p1;
            }
        }
        sum0 += __shfl_xor_sync(0xffffffffu, sum0, 1);
        sum0 += __shfl_xor_sync(0xffffffffu, sum0, 2);
        sum1 += __shfl_xor_sync(0xffffffffu, sum1, 1);
        sum1 += __shfl_xor_sync(0xffffffffu, sum1, 2);
        l0 = l0*al0 + sum0;  m0 = mn0;
        l1 = l1*al1 + sum1;  m1 = mn1;
        #pragma unroll
        for (int nt = 0; nt < 8; nt++) {
            o[nt][0] *= al0; o[nt][1] *= al0;
            o[nt][2] *= al1; o[nt][3] *= al1;
        }

        {
            const int src0 = lr*4 + (lc >> 1);
            const int src1 = src0 + 2;
            const bool odd = lc & 1;
            #pragma unroll
            for (int ks = 0; ks < 8; ks++) {
                const float e0 = __shfl_sync(0xffffffffu, s[ks][0], src0);
                const float e1 = __shfl_sync(0xffffffffu, s[ks][1], src0);
                const float f0 = __shfl_sync(0xffffffffu, s[ks][2], src0);
                const float f1 = __shfl_sync(0xffffffffu, s[ks][3], src0);
                const float g0 = __shfl_sync(0xffffffffu, s[ks][0], src1);
                const float g1 = __shfl_sync(0xffffffffu, s[ks][1], src1);
                const float h0 = __shfl_sync(0xffffffffu, s[ks][2], src1);
                const float h1 = __shfl_sync(0xffffffffu, s[ks][3], src1);
                unsigned pa[4];
                pa[0] = __float_as_uint(odd ? e1 : e0);
                pa[1] = __float_as_uint(odd ? f1 : f0);
                pa[2] = __float_as_uint(odd ? g1 : g0);
                pa[3] = __float_as_uint(odd ? h1 : h0);
                #pragma unroll
                for (int nt = 0; nt < 8; nt++) {
                    unsigned vb[2];
                    vb[0] = __float_as_uint(Vsc[(ks*8 + lc    )*FS + nt*8 + lr]);
                    vb[1] = __float_as_uint(Vsc[(ks*8 + lc + 4)*FS + nt*8 + lr]);
                    mma_tf32(o[nt], pa, vb);
                }
            }
        }
    }

    const float inv0 = 1.0f / l0;
    const float inv1 = 1.0f / l1;
    #pragma unroll
    for (int nt = 0; nt < 8; nt++) {
        const int col = h*HDIM + nt*8 + 2*lc;
        float2 v0, v1;
        v0.x = tf32r(o[nt][0]*inv0); v0.y = tf32r(o[nt][1]*inv0);
        v1.x = tf32r(o[nt][2]*inv1); v1.y = tf32r(o[nt][3]*inv1);
        *(float2*)&g_attn[((size_t)b*SEQ + r0g)*CDIM + col] = v0;
        *(float2*)&g_attn[((size_t)b*SEQ + r1g)*CDIM + col] = v1;
    }
}

// ---------------------------------------------------------------------------
// Kernel 3: proj GEMM [4096,768] @ [768,768] + bias -> out (unchanged)
// ---------------------------------------------------------------------------
#define PAS_SZ (64*36)
#define PBS_SZ (32*136)

__global__ __launch_bounds__(256, 3) void proj_gemm_kernel(
    const float* __restrict__ W,      // [768,768] raw fp32
    const float* __restrict__ bias,
    float* __restrict__ out)
{
    extern __shared__ __align__(16) float ds[];
    float* Asb[2] = { ds, ds + PAS_SZ };
    float* Bsb[2] = { ds + 2*PAS_SZ, ds + 2*PAS_SZ + PBS_SZ };

    const int tid = threadIdx.x;
    const int bn = blockIdx.x;
    const int bm = blockIdx.y;
    const int warp = tid >> 5;
    const int lane = tid & 31;
    const int wm = warp >> 2;
    const int wn = warp & 3;
    const int lr = lane >> 2;
    const int lc = lane & 3;

    float acc[2][4][4];
    #pragma unroll
    for (int mi = 0; mi < 2; mi++)
        #pragma unroll
        for (int ni = 0; ni < 4; ni++)
            #pragma unroll
            for (int q = 0; q < 4; q++) acc[mi][ni][q] = 0.0f;

    const int arow = tid >> 3;
    const int ac4  = (tid & 7) << 2;
    const int brow = tid >> 5;
    const int bc4  = (tid & 31) << 2;

    const float* Ag = g_attn + (size_t)(bm*64)*CDIM;   // already tf32-rounded
    const float* Bg = W + bn*128;

    #pragma unroll
    for (int i = 0; i < 2; i++) {
        const int r = arow + i*32;
        cp_async16(&Asb[0][r*36 + ac4], Ag + (size_t)r*CDIM + ac4);
    }
    #pragma unroll
    for (int i = 0; i < 4; i++) {
        const int r = brow + i*8;
        cp_async16(&Bsb[0][r*136 + bc4], Bg + (size_t)r*CDIM + bc4);
    }
    CP_COMMIT();

    for (int it = 0; it < CDIM/32; it++) {
        const int cur = it & 1;
        CP_WAIT0();
        __syncthreads();

        if (it + 1 < CDIM/32) {
            const int k0 = (it+1)*32;
            #pragma unroll
            for (int i = 0; i < 2; i++) {
                const int r = arow + i*32;
                cp_async16(&Asb[cur^1][r*36 + ac4], Ag + (size_t)r*CDIM + k0 + ac4);
            }
            #pragma unroll
            for (int i = 0; i < 4; i++) {
                const int r = brow + i*8;
                cp_async16(&Bsb[cur^1][r*136 + bc4], Bg + (size_t)(k0 + r)*CDIM + bc4);
            }
            CP_COMMIT();
        }

        const float* As = Asb[cur];
        const float* Bs = Bsb[cur];
        #pragma unroll
        for (int ks = 0; ks < 4; ks++) {
            unsigned a[2][4], b[4][2];
            const int kk = ks*8 + lc;
            #pragma unroll
            for (int mi = 0; mi < 2; mi++) {
                const int row = wm*32 + mi*16 + lr;
                a[mi][0] = __float_as_uint(As[ row   *36 + kk  ]);
                a[mi][1] = __float_as_uint(As[(row+8)*36 + kk  ]);
                a[mi][2] = __float_as_uint(As[ row   *36 + kk+4]);
                a[mi][3] = __float_as_uint(As[(row+8)*36 + kk+4]);
            }
            #pragma unroll
            for (int ni = 0; ni < 4; ni++) {
                const int coln = wn*32 + ni*8 + lr;
                b[ni][0] = tf32u(Bs[(ks*8 + lc    )*136 + coln]);
                b[ni][1] = tf32u(Bs[(ks*8 + lc + 4)*136 + coln]);
            }
            #pragma unroll
            for (int mi = 0; mi < 2; mi++)
                #pragma unroll
                for (int ni = 0; ni < 4; ni++)
                    mma_tf32(acc[mi][ni], a[mi], b[ni]);
        }
        __syncthreads();
    }

    #pragma unroll
    for (int mi = 0; mi < 2; mi++) {
        const int r0 = bm*64 + wm*32 + mi*16 + lr;
        const int r1 = r0 + 8;
        #pragma unroll
        for (int ni = 0; ni < 4; ni++) {
            const int n = bn*128 + wn*32 + ni*8 + 2*lc;
            const float b0 = bias[n], b1 = bias[n+1];
            float2 v0, v1;
            v0.x = acc[mi][ni][0] + b0; v0.y = acc[mi][ni][1] + b1;
            v1.x = acc[mi][ni][2] + b0; v1.y = acc[mi][ni][3] + b1;
            *(float2*)&out[(size_t)r0*CDIM + n] = v0;
            *(float2*)&out[(size_t)r1*CDIM + n] = v1;
        }
    }
}

// ---------------------------------------------------------------------------
extern "C" void kernel_launch(void* const* d_in, const int* in_sizes, int n_in,
                              void* d_out, int out_size)
{
    (void)in_sizes; (void)n_in; (void)out_size;
    const float* x      = (const float*)d_in[0];
    const int*   amask  = (const int*)d_in[1];
    const float* W_attn = (const float*)d_in[2];
    const float* b_attn = (const float*)d_in[3];
    const float* W_proj = (const float*)d_in[4];
    const float* b_proj = (const float*)d_in[5];
    float* out = (float*)d_out;

    const int proj_smem = (2*PAS_SZ + 2*PBS_SZ) * (int)sizeof(float); // 53248 B
    cudaFuncSetAttribute(proj_gemm_kernel,
                         cudaFuncAttributeMaxDynamicSharedMemorySize, proj_smem);
    const int flash_smem = (4*KST + 128) * (int)sizeof(float);        // 70144 B
    cudaFuncSetAttribute(flash_kernel,
                         cudaFuncAttributeMaxDynamicSharedMemorySize, flash_smem);

    {
        dim3 grid(N3/128, MROWS/128);    // (18, 32)
        qkv_gemm_kernel<<<grid, 256>>>(x, W_attn, b_attn);
    }
    {
        dim3 grid(BHN, SEQ/64);          // (24, 32): global heavy-first
        flash_kernel<<<grid, 128, flash_smem>>>(amask);
    }
    {
        dim3 grid(CDIM/128, MROWS/64);   // (6, 64) = 384 blocks
        proj_gemm_kernel<<<grid, 256, proj_smem>>>(W_proj, b_proj, out);
    }
}